// round 2
// baseline (speedup 1.0000x reference)
#include <cuda_runtime.h>
#include <cuda_bf16.h>

// Problem constants (fixed by the dataset)
#define NC  65536   // candidates
#define BSZ 1024    // batch
#define FD  64      // input features
#define DD  512     // model dim
#define DBD 1024    // hidden dim
#define CC  96      // context size

// ---------------- device scratch (allocation-free rule: __device__ globals) ----
__device__ float g_h    [(long)NC*DD];    // candidate h (encoder out)
__device__ float g_t    [(long)NC*DBD];   // relu intermediate / hn reuse
__device__ float g_k    [(long)NC*DD];    // cand_k
__device__ float g_cproj[(long)NC*DBD];   // cand_k @ T_W1
__device__ float g_cnorm[NC];
__device__ float g_d2   [(long)BSZ*NC];

__device__ float g_hx   [BSZ*DD];
__device__ float g_tx   [BSZ*DBD];
__device__ float g_xn   [BSZ*DD];
__device__ float g_kx   [BSZ*DD];
__device__ float g_kproj[BSZ*DBD];
__device__ float g_kxn  [BSZ];
__device__ int   g_idx  [BSZ*CC];
__device__ float g_probs[BSZ*CC];
__device__ float g_ybar [BSZ];
__device__ float g_s    [BSZ*DBD];
__device__ float g_x2   [BSZ*DD];
__device__ float g_x3   [BSZ*DD];

// ---------------- reductions ---------------------------------------------------
__device__ __forceinline__ float blockSum(float v, float* sh) {
    __syncthreads();
    int lane = threadIdx.x & 31, w = threadIdx.x >> 5;
#pragma unroll
    for (int o = 16; o; o >>= 1) v += __shfl_xor_sync(0xffffffffu, v, o);
    if (lane == 0) sh[w] = v;
    __syncthreads();
    if (threadIdx.x == 0) {
        float s = 0.f; int nw = blockDim.x >> 5;
        for (int i = 0; i < nw; i++) s += sh[i];
        sh[32] = s;
    }
    __syncthreads();
    return sh[32];
}

__device__ __forceinline__ float blockMax(float v, float* sh) {
    __syncthreads();
    int lane = threadIdx.x & 31, w = threadIdx.x >> 5;
#pragma unroll
    for (int o = 16; o; o >>= 1) v = fmaxf(v, __shfl_xor_sync(0xffffffffu, v, o));
    if (lane == 0) sh[w] = v;
    __syncthreads();
    if (threadIdx.x == 0) {
        float s = -3.4e38f; int nw = blockDim.x >> 5;
        for (int i = 0; i < nw; i++) s = fmaxf(s, sh[i]);
        sh[32] = s;
    }
    __syncthreads();
    return sh[32];
}

// ---------------- generic tiled SGEMM 128x128x16, 256 thr, 8x8/thread ---------
// MODE 0: C = AB + bias (bias may be null)
// MODE 1: C = relu(AB + bias)
// MODE 2: C = AB + bias + res
// MODE 3: C = rowv[m] + colv[n] - 2*AB            (squared L2 scores)
// MODE 4: C = AB + res + rowv[m]*bias[n] + colv[n] (ctx_x epilogue)
// BT=false: B is [K,N] row-major. BT=true: B is [N,K] row-major (NT gemm).
template<int MODE, bool BT>
__global__ __launch_bounds__(256) void gemm_k(
    int M, int N, int K,
    const float* __restrict__ A, const float* __restrict__ B,
    const float* __restrict__ bias, const float* __restrict__ res,
    const float* __restrict__ rowv, const float* __restrict__ colv,
    float* __restrict__ C)
{
    __shared__ float As[16][128];
    __shared__ float Bs[16][128];
    const int tid = threadIdx.x;
    const int tx = tid & 15, ty = tid >> 4;
    const long rowBase = (long)blockIdx.y * 128;
    const long colBase = (long)blockIdx.x * 128;

    float acc[8][8];
#pragma unroll
    for (int i = 0; i < 8; i++)
#pragma unroll
        for (int j = 0; j < 8; j++) acc[i][j] = 0.f;

    for (int k0 = 0; k0 < K; k0 += 16) {
        // A tile: 128 rows x 16 k, transposed into As[k][row]
#pragma unroll
        for (int i = 0; i < 2; i++) {
            int slot = tid + i * 256;          // 0..511
            int r = slot >> 2, c4 = slot & 3;
            float4 v = *(const float4*)(A + (rowBase + r) * K + k0 + c4 * 4);
            As[c4 * 4 + 0][r] = v.x; As[c4 * 4 + 1][r] = v.y;
            As[c4 * 4 + 2][r] = v.z; As[c4 * 4 + 3][r] = v.w;
        }
        if (!BT) {
#pragma unroll
            for (int i = 0; i < 2; i++) {
                int slot = tid + i * 256;
                int kk = slot >> 5, c4 = slot & 31;
                float4 v = *(const float4*)(B + (long)(k0 + kk) * N + colBase + c4 * 4);
                *(float4*)&Bs[kk][c4 * 4] = v;
            }
        } else {
#pragma unroll
            for (int i = 0; i < 2; i++) {
                int slot = tid + i * 256;
                int cc = slot >> 2, c4 = slot & 3;
                float4 v = *(const float4*)(B + (colBase + cc) * K + k0 + c4 * 4);
                Bs[c4 * 4 + 0][cc] = v.x; Bs[c4 * 4 + 1][cc] = v.y;
                Bs[c4 * 4 + 2][cc] = v.z; Bs[c4 * 4 + 3][cc] = v.w;
            }
        }
        __syncthreads();
#pragma unroll
        for (int kk = 0; kk < 16; kk++) {
            float rm[8], rn[8];
            *(float4*)&rm[0] = *(const float4*)&As[kk][ty * 8];
            *(float4*)&rm[4] = *(const float4*)&As[kk][ty * 8 + 4];
            *(float4*)&rn[0] = *(const float4*)&Bs[kk][tx * 8];
            *(float4*)&rn[4] = *(const float4*)&Bs[kk][tx * 8 + 4];
#pragma unroll
            for (int i = 0; i < 8; i++)
#pragma unroll
                for (int j = 0; j < 8; j++) acc[i][j] += rm[i] * rn[j];
        }
        __syncthreads();
    }

    const long col = colBase + tx * 8;
#pragma unroll
    for (int i = 0; i < 8; i++) {
        const long r = rowBase + ty * 8 + i;
        float* Cp = C + r * N + col;
        float o[8];
#pragma unroll
        for (int j = 0; j < 8; j++) o[j] = acc[i][j];
        if (MODE == 0 || MODE == 1 || MODE == 2) {
            if (bias) {
#pragma unroll
                for (int j = 0; j < 8; j++) o[j] += bias[col + j];
            }
        }
        if (MODE == 2) {
#pragma unroll
            for (int j = 0; j < 8; j++) o[j] += res[r * N + col + j];
        }
        if (MODE == 1) {
#pragma unroll
            for (int j = 0; j < 8; j++) o[j] = fmaxf(o[j], 0.f);
        }
        if (MODE == 3) {
            float rv = rowv[r];
#pragma unroll
            for (int j = 0; j < 8; j++) o[j] = rv + colv[col + j] - 2.f * o[j];
        }
        if (MODE == 4) {
            float rv = rowv[r];
#pragma unroll
            for (int j = 0; j < 8; j++)
                o[j] = o[j] + res[r * N + col + j] + rv * bias[col + j] + colv[col + j];
        }
        *(float4*)Cp       = make_float4(o[0], o[1], o[2], o[3]);
        *(float4*)(Cp + 4) = make_float4(o[4], o[5], o[6], o[7]);
    }
}

// ---------------- layernorm (width 512), 256 threads x 2 elems ----------------
__global__ void ln512_k(const float* __restrict__ in, const float* __restrict__ g,
                        const float* __restrict__ b, float* __restrict__ out)
{
    __shared__ float sh[33];
    const long row = blockIdx.x;
    const float* x = in + row * DD;
    float* o = out + row * DD;
    int t = threadIdx.x;
    float a = x[t], c = x[t + 256];
    float m = blockSum(a + c, sh) * (1.f / DD);
    float d0 = a - m, d1 = c - m;
    float var = blockSum(d0 * d0 + d1 * d1, sh) * (1.f / DD);
    float inv = rsqrtf(var + 1e-5f);
    o[t]       = d0 * inv * g[t]       + b[t];
    o[t + 256] = d1 * inv * g[t + 256] + b[t + 256];
}

// ---------------- row squared-norms (width 512) --------------------------------
__global__ void rownorm512_k(const float* __restrict__ in, float* __restrict__ out)
{
    __shared__ float sh[33];
    const long row = blockIdx.x;
    const float* x = in + row * DD;
    int t = threadIdx.x;
    float a = x[t], c = x[t + 256];
    float s = blockSum(a * a + c * c, sh);
    if (t == 0) out[row] = s;
}

// ---------------- top-96 via 8-bit radix select on monotone float keys --------
__device__ __forceinline__ unsigned fkey(float f) {
    unsigned u = __float_as_uint(f);
    return (u & 0x80000000u) ? ~u : (u | 0x80000000u);
}

__global__ void topk96_k(const float* __restrict__ d2, int* __restrict__ idxo)
{
    const int b = blockIdx.x;
    const float* row = d2 + (long)b * NC;
    __shared__ int hist[256];
    __shared__ unsigned s_prefix;
    __shared__ int s_k, s_below;
    const int tid = threadIdx.x;
    if (tid == 0) { s_prefix = 0u; s_k = CC; s_below = 0; }
    __syncthreads();

#pragma unroll
    for (int p = 0; p < 4; p++) {
        const int shift = 24 - p * 8;
        const unsigned pmask = (p == 0) ? 0u : (0xFFFFFFFFu << (shift + 8));
        hist[tid] = 0;
        __syncthreads();
        const unsigned pref = s_prefix;
        for (int i = tid; i < NC; i += 256) {
            unsigned u = fkey(row[i]);
            if ((u & pmask) == pref) atomicAdd(&hist[(u >> shift) & 255], 1);
        }
        __syncthreads();
        if (tid == 0) {
            int cum = 0, kk = s_k;
            for (int bin = 0; bin < 256; bin++) {
                int h = hist[bin];
                if (cum + h >= kk) {
                    s_prefix = pref | ((unsigned)bin << shift);
                    s_k = kk - cum;
                    s_below += cum;
                    break;
                }
                cum += h;
            }
        }
        __syncthreads();
    }
    const unsigned T = s_prefix;
    const int below = s_below;
    __shared__ int cl, ce;
    if (tid == 0) { cl = 0; ce = 0; }
    __syncthreads();
    for (int i = tid; i < NC; i += 256) {
        unsigned u = fkey(row[i]);
        if (u < T) {
            int pos = atomicAdd(&cl, 1);
            idxo[b * CC + pos] = i;
        } else if (u == T) {
            int pos = atomicAdd(&ce, 1);
            if (below + pos < CC) idxo[b * CC + below + pos] = i;
        }
    }
}

// ---------------- softmax over gathered sims + ybar -----------------------------
__global__ void softmax96_k(const float* __restrict__ d2, const int* __restrict__ idx,
                            const float* __restrict__ cy, float* __restrict__ probs,
                            float* __restrict__ ybar)
{
    __shared__ float sh[33];
    const int b = blockIdx.x, t = threadIdx.x;   // 128 threads
    int id = (t < CC) ? idx[b * CC + t] : 0;
    float sim = (t < CC) ? -d2[(long)b * NC + id] : -3.4e38f;
    float mx = blockMax(sim, sh);
    float e = (t < CC) ? expf(sim - mx) : 0.f;
    float s = blockSum(e, sh);
    float p = e / s;
    if (t < CC) probs[b * CC + t] = p;
    float yv = (t < CC) ? p * cy[id] : 0.f;
    float yb = blockSum(yv, sh);
    if (t == 0) ybar[b] = yb;
}

// ---------------- s[b,:] = sum_c probs * relu(kproj - cproj[idx]) ---------------
__global__ void ctxsum_k(const float* __restrict__ kproj, const float* __restrict__ cproj,
                         const int* __restrict__ idx, const float* __restrict__ probs,
                         float* __restrict__ s)
{
    const int b = blockIdx.x, j = threadIdx.x;   // 1024 threads
    __shared__ int   si[CC];
    __shared__ float sp[CC];
    if (j < CC) { si[j] = idx[b * CC + j]; sp[j] = probs[b * CC + j]; }
    __syncthreads();
    float kp = kproj[(long)b * DBD + j];
    float acc = 0.f;
#pragma unroll 4
    for (int c = 0; c < CC; c++) {
        float v = kp - cproj[(long)si[c] * DBD + j];
        acc += sp[c] * fmaxf(v, 0.f);
    }
    s[(long)b * DBD + j] = acc;
}

// ---------------- head: relu(ln(x)) @ h_W + h_b ---------------------------------
__global__ void head512_k(const float* __restrict__ in, const float* __restrict__ g,
                          const float* __restrict__ bb, const float* __restrict__ hW,
                          const float* __restrict__ hb, float* __restrict__ out)
{
    __shared__ float sh[33];
    const long row = blockIdx.x;
    const float* x = in + row * DD;
    int t = threadIdx.x;
    float a = x[t], c = x[t + 256];
    float m = blockSum(a + c, sh) * (1.f / DD);
    float d0 = a - m, d1 = c - m;
    float v = blockSum(d0 * d0 + d1 * d1, sh) * (1.f / DD);
    float inv = rsqrtf(v + 1e-5f);
    float s0 = fmaxf(d0 * inv * g[t] + bb[t], 0.f) * hW[t];
    float s1 = fmaxf(d1 * inv * g[t + 256] + bb[t + 256], 0.f) * hW[t + 256];
    float tot = blockSum(s0 + s1, sh);
    if (t == 0) out[row] = tot + hb[0];
}

// ---------------- host side -----------------------------------------------------
template<typename T>
static T* devptr(const void* sym) {
    void* p = nullptr;
    cudaGetSymbolAddress(&p, sym);
    return (T*)p;
}

template<int MODE, bool BT>
static void launch_gemm(int M, int N, int K,
                        const float* A, const float* B,
                        const float* bias, const float* res,
                        const float* rowv, const float* colv, float* C) {
    dim3 grid(N / 128, M / 128);
    gemm_k<MODE, BT><<<grid, 256>>>(M, N, K, A, B, bias, res, rowv, colv, C);
}

extern "C" void kernel_launch(void* const* d_in, const int* in_sizes, int n_in,
                              void* d_out, int out_size)
{
    const float* x_num  = (const float*)d_in[0];
    const float* cand   = (const float*)d_in[1];
    const float* cy     = (const float*)d_in[2];
    const float* lin_W  = (const float*)d_in[3];
    const float* lin_b  = (const float*)d_in[4];
    const float* e_W1   = (const float*)d_in[5];
    const float* e_b1   = (const float*)d_in[6];
    const float* e_W2   = (const float*)d_in[7];
    const float* e_b2   = (const float*)d_in[8];
    const float* mix_g  = (const float*)d_in[9];
    const float* mix_b  = (const float*)d_in[10];
    const float* K_W    = (const float*)d_in[11];
    const float* K_b    = (const float*)d_in[12];
    const float* lab_W  = (const float*)d_in[13];
    const float* lab_b  = (const float*)d_in[14];
    const float* T_W1   = (const float*)d_in[15];
    const float* T_b1   = (const float*)d_in[16];
    const float* T_W2   = (const float*)d_in[17];
    const float* p_ln_g = (const float*)d_in[18];
    const float* p_ln_b = (const float*)d_in[19];
    const float* p_W1   = (const float*)d_in[20];
    const float* p_b1   = (const float*)d_in[21];
    const float* p_W2   = (const float*)d_in[22];
    const float* p_b2   = (const float*)d_in[23];
    const float* h_ln_g = (const float*)d_in[24];
    const float* h_ln_b = (const float*)d_in[25];
    const float* h_W    = (const float*)d_in[26];
    const float* h_b    = (const float*)d_in[27];
    float* out = (float*)d_out;

    float* p_h     = devptr<float>(g_h);
    float* p_t     = devptr<float>(g_t);
    float* p_k     = devptr<float>(g_k);
    float* p_cproj = devptr<float>(g_cproj);
    float* p_cnorm = devptr<float>(g_cnorm);
    float* p_d2    = devptr<float>(g_d2);
    float* p_hx    = devptr<float>(g_hx);
    float* p_tx    = devptr<float>(g_tx);
    float* p_xn    = devptr<float>(g_xn);
    float* p_kx    = devptr<float>(g_kx);
    float* p_kproj = devptr<float>(g_kproj);
    float* p_kxn   = devptr<float>(g_kxn);
    int*   p_idx   = devptr<int>(g_idx);
    float* p_probs = devptr<float>(g_probs);
    float* p_ybar  = devptr<float>(g_ybar);
    float* p_s     = devptr<float>(g_s);
    float* p_x2    = devptr<float>(g_x2);
    float* p_x3    = devptr<float>(g_x3);

    // ---- candidate encoder -----------------------------------------------
    launch_gemm<0, false>(NC, DD, FD, cand, lin_W, lin_b, nullptr, nullptr, nullptr, p_h);
    launch_gemm<1, false>(NC, DBD, DD, p_h, e_W1, e_b1, nullptr, nullptr, nullptr, p_t);
    launch_gemm<2, false>(NC, DD, DBD, p_t, e_W2, e_b2, p_h, nullptr, nullptr, p_h);
    ln512_k<<<NC, 256>>>(p_h, mix_g, mix_b, p_t);                 // hn in p_t
    launch_gemm<0, false>(NC, DD, DD, p_t, K_W, K_b, nullptr, nullptr, nullptr, p_k);
    launch_gemm<0, false>(NC, DBD, DD, p_k, T_W1, nullptr, nullptr, nullptr, nullptr, p_cproj);
    rownorm512_k<<<NC, 256>>>(p_k, p_cnorm);

    // ---- query encoder ----------------------------------------------------
    launch_gemm<0, false>(BSZ, DD, FD, x_num, lin_W, lin_b, nullptr, nullptr, nullptr, p_hx);
    launch_gemm<1, false>(BSZ, DBD, DD, p_hx, e_W1, e_b1, nullptr, nullptr, nullptr, p_tx);
    launch_gemm<2, false>(BSZ, DD, DBD, p_tx, e_W2, e_b2, p_hx, nullptr, nullptr, p_hx);
    ln512_k<<<BSZ, 256>>>(p_hx, mix_g, mix_b, p_xn);
    launch_gemm<0, false>(BSZ, DD, DD, p_xn, K_W, K_b, nullptr, nullptr, nullptr, p_kx);
    launch_gemm<0, false>(BSZ, DBD, DD, p_kx, T_W1, T_b1, nullptr, nullptr, nullptr, p_kproj);
    rownorm512_k<<<BSZ, 256>>>(p_kx, p_kxn);

    // ---- kNN scores + top-96 ----------------------------------------------
    launch_gemm<3, true>(BSZ, NC, DD, p_kx, p_k, nullptr, nullptr, p_kxn, p_cnorm, p_d2);
    topk96_k<<<BSZ, 256>>>(p_d2, p_idx);
    softmax96_k<<<BSZ, 128>>>(p_d2, p_idx, cy, p_probs, p_ybar);

    // ---- context aggregation ----------------------------------------------
    ctxsum_k<<<BSZ, 1024>>>(p_kproj, p_cproj, p_idx, p_probs, p_s);
    launch_gemm<4, false>(BSZ, DD, DBD, p_s, T_W2, lab_W, p_hx, p_ybar, lab_b, p_x2);

    // ---- predictor block + head -------------------------------------------
    ln512_k<<<BSZ, 256>>>(p_x2, p_ln_g, p_ln_b, p_xn);
    launch_gemm<1, false>(BSZ, DBD, DD, p_xn, p_W1, p_b1, nullptr, nullptr, nullptr, p_tx);
    launch_gemm<2, false>(BSZ, DD, DBD, p_tx, p_W2, p_b2, p_x2, nullptr, nullptr, p_x3);
    head512_k<<<BSZ, 256>>>(p_x3, h_ln_g, h_ln_b, h_W, h_b, out);

    (void)in_sizes; (void)n_in; (void)out_size;
}

// round 4
// speedup vs baseline: 1.1871x; 1.1871x over previous
#include <cuda_runtime.h>
#include <cuda_bf16.h>

// Problem constants (fixed by the dataset)
#define NC  65536   // candidates
#define BSZ 1024    // batch
#define FD  64      // input features
#define DD  512     // model dim
#define DBD 1024    // hidden dim
#define CC  96      // context size

// ---------------- device scratch (allocation-free rule: __device__ globals) ----
__device__ float g_h    [(long)NC*DD];
__device__ float g_t    [(long)NC*DBD];
__device__ float g_k    [(long)NC*DD];
__device__ float g_cproj[(long)NC*DBD];
__device__ float g_cnorm[NC];
__device__ float g_d2   [(long)BSZ*NC];

__device__ float g_hx   [BSZ*DD];
__device__ float g_tx   [BSZ*DBD];
__device__ float g_xn   [BSZ*DD];
__device__ float g_kx   [BSZ*DD];
__device__ float g_kproj[BSZ*DBD];
__device__ float g_kxn  [BSZ];
__device__ int   g_idx  [BSZ*CC];
__device__ float g_probs[BSZ*CC];
__device__ float g_ybar [BSZ];
__device__ float g_s    [BSZ*DBD];
__device__ float g_x2   [BSZ*DD];
__device__ float g_x3   [BSZ*DD];

// ---------------- helpers -------------------------------------------------------
__device__ __forceinline__ void split_pack(float x, float y, unsigned &hi, unsigned &lo) {
    __nv_bfloat16 xh = __float2bfloat16_rn(x);
    __nv_bfloat16 yh = __float2bfloat16_rn(y);
    __nv_bfloat16 xl = __float2bfloat16_rn(x - __bfloat162float(xh));
    __nv_bfloat16 yl = __float2bfloat16_rn(y - __bfloat162float(yh));
    hi = ((unsigned)__bfloat16_as_ushort(yh) << 16) | (unsigned)__bfloat16_as_ushort(xh);
    lo = ((unsigned)__bfloat16_as_ushort(yl) << 16) | (unsigned)__bfloat16_as_ushort(xl);
}

__device__ __forceinline__ void split1(float x, __nv_bfloat16 &h, __nv_bfloat16 &l) {
    h = __float2bfloat16_rn(x);
    l = __float2bfloat16_rn(x - __bfloat162float(h));
}

__device__ __forceinline__ void mma_bf16(float c[4], const unsigned a[4], const unsigned b[2]) {
    asm volatile(
        "mma.sync.aligned.m16n8k16.row.col.f32.bf16.bf16.f32 "
        "{%0,%1,%2,%3}, {%4,%5,%6,%7}, {%8,%9}, {%0,%1,%2,%3};"
        : "+f"(c[0]), "+f"(c[1]), "+f"(c[2]), "+f"(c[3])
        : "r"(a[0]), "r"(a[1]), "r"(a[2]), "r"(a[3]), "r"(b[0]), "r"(b[1]));
}

__device__ __forceinline__ float blockSum(float v, float* sh) {
    __syncthreads();
    int lane = threadIdx.x & 31, w = threadIdx.x >> 5;
#pragma unroll
    for (int o = 16; o; o >>= 1) v += __shfl_xor_sync(0xffffffffu, v, o);
    if (lane == 0) sh[w] = v;
    __syncthreads();
    if (threadIdx.x == 0) {
        float s = 0.f; int nw = blockDim.x >> 5;
        for (int i = 0; i < nw; i++) s += sh[i];
        sh[32] = s;
    }
    __syncthreads();
    return sh[32];
}

__device__ __forceinline__ float blockMax(float v, float* sh) {
    __syncthreads();
    int lane = threadIdx.x & 31, w = threadIdx.x >> 5;
#pragma unroll
    for (int o = 16; o; o >>= 1) v = fmaxf(v, __shfl_xor_sync(0xffffffffu, v, o));
    if (lane == 0) sh[w] = v;
    __syncthreads();
    if (threadIdx.x == 0) {
        float s = -3.4e38f; int nw = blockDim.x >> 5;
        for (int i = 0; i < nw; i++) s = fmaxf(s, sh[i]);
        sh[32] = s;
    }
    __syncthreads();
    return sh[32];
}

// ---------------- bf16x4 error-compensated tensor-core GEMM --------------------
// 128x128 block, kTile=16, 8 warps 2(M)x4(N), warp tile 64x32, mma m16n8k16.
// Each fp32 operand split into hi+lo bf16; all 4 partial products accumulated
// in fp32 => effectively fp32-accurate GEMM on the tensor pipe.
// MODE 0: C = AB + bias (bias may be null)
// MODE 1: C = relu(AB + bias)
// MODE 2: C = AB + bias + res
// MODE 3: C = rowv[m] + colv[n] - 2*AB
// MODE 4: C = AB + res + rowv[m]*bias[n] + colv[n]
// BT=false: B is [K,N] row-major.  BT=true: B is [N,K] row-major.
template<int MODE, bool BT>
__global__ __launch_bounds__(256) void gemm_bf16x4_k(
    int M, int N, int K,
    const float* __restrict__ A, const float* __restrict__ B,
    const float* __restrict__ bias, const float* __restrict__ res,
    const float* __restrict__ rowv, const float* __restrict__ colv,
    float* __restrict__ C)
{
    // pitch 20 bf16 (40B) keeps fragment loads mostly conflict-free
    __shared__ __align__(16) __nv_bfloat16 Ah[2][128][20];
    __shared__ __align__(16) __nv_bfloat16 Al[2][128][20];
    __shared__ __align__(16) __nv_bfloat16 Bh[2][128][20];
    __shared__ __align__(16) __nv_bfloat16 Bl[2][128][20];

    const int tid  = threadIdx.x;
    const int lane = tid & 31;
    const int wid  = tid >> 5;
    const int wm   = (wid & 1) * 64;
    const int wn   = (wid >> 1) * 32;
    const int grp  = lane >> 2;    // 0..7
    const int thr  = lane & 3;     // 0..3

    const long rowBase = (long)blockIdx.y * 128;
    const long colBase = (long)blockIdx.x * 128;

    float acc[4][4][4];
#pragma unroll
    for (int mi = 0; mi < 4; mi++)
#pragma unroll
        for (int ni = 0; ni < 4; ni++)
#pragma unroll
            for (int j = 0; j < 4; j++) acc[mi][ni][j] = 0.f;

    const int T = K >> 4;          // kTile = 16
    float4 av[2], bv[2];

    // ---- fill buffer 0 ----------------------------------------------------
    {
#pragma unroll
        for (int i = 0; i < 2; i++) {
            int q = tid + i * 256;
            int r = q >> 2, c4 = q & 3;
            float4 v = *(const float4*)(A + (rowBase + r) * K + c4 * 4);
            unsigned h0, l0, h1, l1;
            split_pack(v.x, v.y, h0, l0);
            split_pack(v.z, v.w, h1, l1);
            *(unsigned*)&Ah[0][r][c4 * 4]     = h0;
            *(unsigned*)&Ah[0][r][c4 * 4 + 2] = h1;
            *(unsigned*)&Al[0][r][c4 * 4]     = l0;
            *(unsigned*)&Al[0][r][c4 * 4 + 2] = l1;
        }
        if (BT) {
#pragma unroll
            for (int i = 0; i < 2; i++) {
                int q = tid + i * 256;
                int n = q >> 2, c4 = q & 3;
                float4 v = *(const float4*)(B + (colBase + n) * K + c4 * 4);
                unsigned h0, l0, h1, l1;
                split_pack(v.x, v.y, h0, l0);
                split_pack(v.z, v.w, h1, l1);
                *(unsigned*)&Bh[0][n][c4 * 4]     = h0;
                *(unsigned*)&Bh[0][n][c4 * 4 + 2] = h1;
                *(unsigned*)&Bl[0][n][c4 * 4]     = l0;
                *(unsigned*)&Bl[0][n][c4 * 4 + 2] = l1;
            }
        } else {
#pragma unroll
            for (int i = 0; i < 2; i++) {
                int q = tid + i * 256;
                int kr = q >> 5, n4 = q & 31;
                float4 v = *(const float4*)(B + (long)kr * N + colBase + n4 * 4);
                __nv_bfloat16 h, l;
                split1(v.x, h, l); Bh[0][n4*4+0][kr] = h; Bl[0][n4*4+0][kr] = l;
                split1(v.y, h, l); Bh[0][n4*4+1][kr] = h; Bl[0][n4*4+1][kr] = l;
                split1(v.z, h, l); Bh[0][n4*4+2][kr] = h; Bl[0][n4*4+2][kr] = l;
                split1(v.w, h, l); Bh[0][n4*4+3][kr] = h; Bl[0][n4*4+3][kr] = l;
            }
        }
    }
    __syncthreads();

    for (int t = 0; t < T; t++) {
        const int cur = t & 1, nxt = cur ^ 1;
        const bool more = (t + 1 < T);

        // ---- issue global loads for next tile -----------------------------
        if (more) {
            const int k0 = (t + 1) << 4;
#pragma unroll
            for (int i = 0; i < 2; i++) {
                int q = tid + i * 256;
                int r = q >> 2, c4 = q & 3;
                av[i] = *(const float4*)(A + (rowBase + r) * K + k0 + c4 * 4);
            }
            if (BT) {
#pragma unroll
                for (int i = 0; i < 2; i++) {
                    int q = tid + i * 256;
                    int n = q >> 2, c4 = q & 3;
                    bv[i] = *(const float4*)(B + (colBase + n) * K + k0 + c4 * 4);
                }
            } else {
#pragma unroll
                for (int i = 0; i < 2; i++) {
                    int q = tid + i * 256;
                    int kr = q >> 5, n4 = q & 31;
                    bv[i] = *(const float4*)(B + (long)(k0 + kr) * N + colBase + n4 * 4);
                }
            }
        }

        // ---- compute on current tile (one k16 step) ------------------------
        {
            unsigned ah[4][4], al[4][4], bh[4][2], bl[4][2];
#pragma unroll
            for (int mi = 0; mi < 4; mi++) {
                int m = wm + mi * 16 + grp;
                ah[mi][0] = *(const unsigned*)&Ah[cur][m][2 * thr];
                ah[mi][1] = *(const unsigned*)&Ah[cur][m + 8][2 * thr];
                ah[mi][2] = *(const unsigned*)&Ah[cur][m][2 * thr + 8];
                ah[mi][3] = *(const unsigned*)&Ah[cur][m + 8][2 * thr + 8];
                al[mi][0] = *(const unsigned*)&Al[cur][m][2 * thr];
                al[mi][1] = *(const unsigned*)&Al[cur][m + 8][2 * thr];
                al[mi][2] = *(const unsigned*)&Al[cur][m][2 * thr + 8];
                al[mi][3] = *(const unsigned*)&Al[cur][m + 8][2 * thr + 8];
            }
#pragma unroll
            for (int ni = 0; ni < 4; ni++) {
                int n = wn + ni * 8 + grp;
                bh[ni][0] = *(const unsigned*)&Bh[cur][n][2 * thr];
                bh[ni][1] = *(const unsigned*)&Bh[cur][n][2 * thr + 8];
                bl[ni][0] = *(const unsigned*)&Bl[cur][n][2 * thr];
                bl[ni][1] = *(const unsigned*)&Bl[cur][n][2 * thr + 8];
            }
#pragma unroll
            for (int mi = 0; mi < 4; mi++)
#pragma unroll
                for (int ni = 0; ni < 4; ni++) {
                    mma_bf16(acc[mi][ni], ah[mi], bh[ni]);
                    mma_bf16(acc[mi][ni], ah[mi], bl[ni]);
                    mma_bf16(acc[mi][ni], al[mi], bh[ni]);
                    mma_bf16(acc[mi][ni], al[mi], bl[ni]);
                }
        }

        // ---- split+store next tile -----------------------------------------
        if (more) {
#pragma unroll
            for (int i = 0; i < 2; i++) {
                int q = tid + i * 256;
                int r = q >> 2, c4 = q & 3;
                unsigned h0, l0, h1, l1;
                split_pack(av[i].x, av[i].y, h0, l0);
                split_pack(av[i].z, av[i].w, h1, l1);
                *(unsigned*)&Ah[nxt][r][c4 * 4]     = h0;
                *(unsigned*)&Ah[nxt][r][c4 * 4 + 2] = h1;
                *(unsigned*)&Al[nxt][r][c4 * 4]     = l0;
                *(unsigned*)&Al[nxt][r][c4 * 4 + 2] = l1;
            }
            if (BT) {
#pragma unroll
                for (int i = 0; i < 2; i++) {
                    int q = tid + i * 256;
                    int n = q >> 2, c4 = q & 3;
                    unsigned h0, l0, h1, l1;
                    split_pack(bv[i].x, bv[i].y, h0, l0);
                    split_pack(bv[i].z, bv[i].w, h1, l1);
                    *(unsigned*)&Bh[nxt][n][c4 * 4]     = h0;
                    *(unsigned*)&Bh[nxt][n][c4 * 4 + 2] = h1;
                    *(unsigned*)&Bl[nxt][n][c4 * 4]     = l0;
                    *(unsigned*)&Bl[nxt][n][c4 * 4 + 2] = l1;
                }
            } else {
#pragma unroll
                for (int i = 0; i < 2; i++) {
                    int q = tid + i * 256;
                    int kr = q >> 5, n4 = q & 31;
                    __nv_bfloat16 h, l;
                    split1(bv[i].x, h, l); Bh[nxt][n4*4+0][kr] = h; Bl[nxt][n4*4+0][kr] = l;
                    split1(bv[i].y, h, l); Bh[nxt][n4*4+1][kr] = h; Bl[nxt][n4*4+1][kr] = l;
                    split1(bv[i].z, h, l); Bh[nxt][n4*4+2][kr] = h; Bl[nxt][n4*4+2][kr] = l;
                    split1(bv[i].w, h, l); Bh[nxt][n4*4+3][kr] = h; Bl[nxt][n4*4+3][kr] = l;
                }
            }
        }
        __syncthreads();
    }

    // ---- epilogue --------------------------------------------------------
#pragma unroll
    for (int mi = 0; mi < 4; mi++) {
#pragma unroll
        for (int half = 0; half < 2; half++) {
            const long r = rowBase + wm + mi * 16 + grp + half * 8;
            const float rv = (MODE == 3 || MODE == 4) ? rowv[r] : 0.f;
#pragma unroll
            for (int ni = 0; ni < 4; ni++) {
                const long c = colBase + wn + ni * 8 + thr * 2;
                float o0 = acc[mi][ni][half * 2 + 0];
                float o1 = acc[mi][ni][half * 2 + 1];
                if (MODE == 0 || MODE == 1 || MODE == 2) {
                    if (bias) { o0 += bias[c]; o1 += bias[c + 1]; }
                }
                if (MODE == 2) {
                    o0 += res[r * N + c]; o1 += res[r * N + c + 1];
                }
                if (MODE == 1) { o0 = fmaxf(o0, 0.f); o1 = fmaxf(o1, 0.f); }
                if (MODE == 3) {
                    o0 = rv + colv[c]     - 2.f * o0;
                    o1 = rv + colv[c + 1] - 2.f * o1;
                }
                if (MODE == 4) {
                    o0 = o0 + res[r * N + c]     + rv * bias[c]     + colv[c];
                    o1 = o1 + res[r * N + c + 1] + rv * bias[c + 1] + colv[c + 1];
                }
                *(float2*)(C + r * N + c) = make_float2(o0, o1);
            }
        }
    }
}

// ---------------- layernorm (width 512), 256 threads x 2 elems ----------------
__global__ void ln512_k(const float* __restrict__ in, const float* __restrict__ g,
                        const float* __restrict__ b, float* __restrict__ out)
{
    __shared__ float sh[33];
    const long row = blockIdx.x;
    const float* x = in + row * DD;
    float* o = out + row * DD;
    int t = threadIdx.x;
    float a = x[t], c = x[t + 256];
    float m = blockSum(a + c, sh) * (1.f / DD);
    float d0 = a - m, d1 = c - m;
    float var = blockSum(d0 * d0 + d1 * d1, sh) * (1.f / DD);
    float inv = rsqrtf(var + 1e-5f);
    o[t]       = d0 * inv * g[t]       + b[t];
    o[t + 256] = d1 * inv * g[t + 256] + b[t + 256];
}

// ---------------- row squared-norms (width 512) --------------------------------
__global__ void rownorm512_k(const float* __restrict__ in, float* __restrict__ out)
{
    __shared__ float sh[33];
    const long row = blockIdx.x;
    const float* x = in + row * DD;
    int t = threadIdx.x;
    float a = x[t], c = x[t + 256];
    float s = blockSum(a * a + c * c, sh);
    if (t == 0) out[row] = s;
}

// ---------------- top-96 via 8-bit radix select on monotone float keys --------
__device__ __forceinline__ unsigned fkey(float f) {
    unsigned u = __float_as_uint(f);
    return (u & 0x80000000u) ? ~u : (u | 0x80000000u);
}

__global__ void topk96_k(const float* __restrict__ d2, int* __restrict__ idxo)
{
    const int b = blockIdx.x;
    const float* row = d2 + (long)b * NC;
    __shared__ int hist[256];
    __shared__ unsigned s_prefix;
    __shared__ int s_k, s_below;
    const int tid = threadIdx.x;
    if (tid == 0) { s_prefix = 0u; s_k = CC; s_below = 0; }
    __syncthreads();

#pragma unroll
    for (int p = 0; p < 4; p++) {
        const int shift = 24 - p * 8;
        const unsigned pmask = (p == 0) ? 0u : (0xFFFFFFFFu << (shift + 8));
        hist[tid] = 0;
        __syncthreads();
        const unsigned pref = s_prefix;
        for (int i = tid; i < NC; i += 256) {
            unsigned u = fkey(row[i]);
            if ((u & pmask) == pref) atomicAdd(&hist[(u >> shift) & 255], 1);
        }
        __syncthreads();
        if (tid == 0) {
            int cum = 0, kk = s_k;
            for (int bin = 0; bin < 256; bin++) {
                int h = hist[bin];
                if (cum + h >= kk) {
                    s_prefix = pref | ((unsigned)bin << shift);
                    s_k = kk - cum;
                    s_below += cum;
                    break;
                }
                cum += h;
            }
        }
        __syncthreads();
    }
    const unsigned T = s_prefix;
    const int below = s_below;
    __shared__ int cl, ce;
    if (tid == 0) { cl = 0; ce = 0; }
    __syncthreads();
    for (int i = tid; i < NC; i += 256) {
        unsigned u = fkey(row[i]);
        if (u < T) {
            int pos = atomicAdd(&cl, 1);
            idxo[b * CC + pos] = i;
        } else if (u == T) {
            int pos = atomicAdd(&ce, 1);
            if (below + pos < CC) idxo[b * CC + below + pos] = i;
        }
    }
}

// ---------------- softmax over gathered sims + ybar -----------------------------
__global__ void softmax96_k(const float* __restrict__ d2, const int* __restrict__ idx,
                            const float* __restrict__ cy, float* __restrict__ probs,
                            float* __restrict__ ybar)
{
    __shared__ float sh[33];
    const int b = blockIdx.x, t = threadIdx.x;   // 128 threads
    int id = (t < CC) ? idx[b * CC + t] : 0;
    float sim = (t < CC) ? -d2[(long)b * NC + id] : -3.4e38f;
    float mx = blockMax(sim, sh);
    float e = (t < CC) ? expf(sim - mx) : 0.f;
    float s = blockSum(e, sh);
    float p = e / s;
    if (t < CC) probs[b * CC + t] = p;
    float yv = (t < CC) ? p * cy[id] : 0.f;
    float yb = blockSum(yv, sh);
    if (t == 0) ybar[b] = yb;
}

// ---------------- s[b,:] = sum_c probs * relu(kproj - cproj[idx]) ---------------
__global__ void ctxsum_k(const float* __restrict__ kproj, const float* __restrict__ cproj,
                         const int* __restrict__ idx, const float* __restrict__ probs,
                         float* __restrict__ s)
{
    const int b = blockIdx.x, j = threadIdx.x;   // 1024 threads
    __shared__ int   si[CC];
    __shared__ float sp[CC];
    if (j < CC) { si[j] = idx[b * CC + j]; sp[j] = probs[b * CC + j]; }
    __syncthreads();
    float kp = kproj[(long)b * DBD + j];
    float acc = 0.f;
#pragma unroll 4
    for (int c = 0; c < CC; c++) {
        float v = kp - cproj[(long)si[c] * DBD + j];
        acc += sp[c] * fmaxf(v, 0.f);
    }
    s[(long)b * DBD + j] = acc;
}

// ---------------- head: relu(ln(x)) @ h_W + h_b ---------------------------------
__global__ void head512_k(const float* __restrict__ in, const float* __restrict__ g,
                          const float* __restrict__ bb, const float* __restrict__ hW,
                          const float* __restrict__ hb, float* __restrict__ out)
{
    __shared__ float sh[33];
    const long row = blockIdx.x;
    const float* x = in + row * DD;
    int t = threadIdx.x;
    float a = x[t], c = x[t + 256];
    float m = blockSum(a + c, sh) * (1.f / DD);
    float d0 = a - m, d1 = c - m;
    float v = blockSum(d0 * d0 + d1 * d1, sh) * (1.f / DD);
    float inv = rsqrtf(v + 1e-5f);
    float s0 = fmaxf(d0 * inv * g[t] + bb[t], 0.f) * hW[t];
    float s1 = fmaxf(d1 * inv * g[t + 256] + bb[t + 256], 0.f) * hW[t + 256];
    float tot = blockSum(s0 + s1, sh);
    if (t == 0) out[row] = tot + hb[0];
}

// ---------------- host side -----------------------------------------------------
template<typename T>
static T* devptr(const void* sym) {
    void* p = nullptr;
    cudaGetSymbolAddress(&p, sym);
    return (T*)p;
}

template<int MODE, bool BT>
static void launch_gemm(int M, int N, int K,
                        const float* A, const float* B,
                        const float* bias, const float* res,
                        const float* rowv, const float* colv, float* C) {
    dim3 grid(N / 128, M / 128);
    gemm_bf16x4_k<MODE, BT><<<grid, 256>>>(M, N, K, A, B, bias, res, rowv, colv, C);
}

extern "C" void kernel_launch(void* const* d_in, const int* in_sizes, int n_in,
                              void* d_out, int out_size)
{
    const float* x_num  = (const float*)d_in[0];
    const float* cand   = (const float*)d_in[1];
    const float* cy     = (const float*)d_in[2];
    const float* lin_W  = (const float*)d_in[3];
    const float* lin_b  = (const float*)d_in[4];
    const float* e_W1   = (const float*)d_in[5];
    const float* e_b1   = (const float*)d_in[6];
    const float* e_W2   = (const float*)d_in[7];
    const float* e_b2   = (const float*)d_in[8];
    const float* mix_g  = (const float*)d_in[9];
    const float* mix_b  = (const float*)d_in[10];
    const float* K_W    = (const float*)d_in[11];
    const float* K_b    = (const float*)d_in[12];
    const float* lab_W  = (const float*)d_in[13];
    const float* lab_b  = (const float*)d_in[14];
    const float* T_W1   = (const float*)d_in[15];
    const float* T_b1   = (const float*)d_in[16];
    const float* T_W2   = (const float*)d_in[17];
    const float* p_ln_g = (const float*)d_in[18];
    const float* p_ln_b = (const float*)d_in[19];
    const float* p_W1   = (const float*)d_in[20];
    const float* p_b1   = (const float*)d_in[21];
    const float* p_W2   = (const float*)d_in[22];
    const float* p_b2   = (const float*)d_in[23];
    const float* h_ln_g = (const float*)d_in[24];
    const float* h_ln_b = (const float*)d_in[25];
    const float* h_W    = (const float*)d_in[26];
    const float* h_b    = (const float*)d_in[27];
    float* out = (float*)d_out;

    float* p_h     = devptr<float>(g_h);
    float* p_t     = devptr<float>(g_t);
    float* p_k     = devptr<float>(g_k);
    float* p_cproj = devptr<float>(g_cproj);
    float* p_cnorm = devptr<float>(g_cnorm);
    float* p_d2    = devptr<float>(g_d2);
    float* p_hx    = devptr<float>(g_hx);
    float* p_tx    = devptr<float>(g_tx);
    float* p_xn    = devptr<float>(g_xn);
    float* p_kx    = devptr<float>(g_kx);
    float* p_kproj = devptr<float>(g_kproj);
    float* p_kxn   = devptr<float>(g_kxn);
    int*   p_idx   = devptr<int>(g_idx);
    float* p_probs = devptr<float>(g_probs);
    float* p_ybar  = devptr<float>(g_ybar);
    float* p_s     = devptr<float>(g_s);
    float* p_x2    = devptr<float>(g_x2);
    float* p_x3    = devptr<float>(g_x3);

    // ---- candidate encoder -----------------------------------------------
    launch_gemm<0, false>(NC, DD, FD, cand, lin_W, lin_b, nullptr, nullptr, nullptr, p_h);
    launch_gemm<1, false>(NC, DBD, DD, p_h, e_W1, e_b1, nullptr, nullptr, nullptr, p_t);
    launch_gemm<2, false>(NC, DD, DBD, p_t, e_W2, e_b2, p_h, nullptr, nullptr, p_h);
    ln512_k<<<NC, 256>>>(p_h, mix_g, mix_b, p_t);                 // hn in p_t
    launch_gemm<0, false>(NC, DD, DD, p_t, K_W, K_b, nullptr, nullptr, nullptr, p_k);
    launch_gemm<0, false>(NC, DBD, DD, p_k, T_W1, nullptr, nullptr, nullptr, nullptr, p_cproj);
    rownorm512_k<<<NC, 256>>>(p_k, p_cnorm);

    // ---- query encoder ----------------------------------------------------
    launch_gemm<0, false>(BSZ, DD, FD, x_num, lin_W, lin_b, nullptr, nullptr, nullptr, p_hx);
    launch_gemm<1, false>(BSZ, DBD, DD, p_hx, e_W1, e_b1, nullptr, nullptr, nullptr, p_tx);
    launch_gemm<2, false>(BSZ, DD, DBD, p_tx, e_W2, e_b2, p_hx, nullptr, nullptr, p_hx);
    ln512_k<<<BSZ, 256>>>(p_hx, mix_g, mix_b, p_xn);
    launch_gemm<0, false>(BSZ, DD, DD, p_xn, K_W, K_b, nullptr, nullptr, nullptr, p_kx);
    launch_gemm<0, false>(BSZ, DBD, DD, p_kx, T_W1, T_b1, nullptr, nullptr, nullptr, p_kproj);
    rownorm512_k<<<BSZ, 256>>>(p_kx, p_kxn);

    // ---- kNN scores + top-96 ----------------------------------------------
    launch_gemm<3, true>(BSZ, NC, DD, p_kx, p_k, nullptr, nullptr, p_kxn, p_cnorm, p_d2);
    topk96_k<<<BSZ, 256>>>(p_d2, p_idx);
    softmax96_k<<<BSZ, 128>>>(p_d2, p_idx, cy, p_probs, p_ybar);

    // ---- context aggregation ----------------------------------------------
    ctxsum_k<<<BSZ, 1024>>>(p_kproj, p_cproj, p_idx, p_probs, p_s);
    launch_gemm<4, false>(BSZ, DD, DBD, p_s, T_W2, lab_W, p_hx, p_ybar, lab_b, p_x2);

    // ---- predictor block + head -------------------------------------------
    ln512_k<<<BSZ, 256>>>(p_x2, p_ln_g, p_ln_b, p_xn);
    launch_gemm<1, false>(BSZ, DBD, DD, p_xn, p_W1, p_b1, nullptr, nullptr, nullptr, p_tx);
    launch_gemm<2, false>(BSZ, DD, DBD, p_tx, p_W2, p_b2, p_x2, nullptr, nullptr, p_x3);
    head512_k<<<BSZ, 256>>>(p_x3, h_ln_g, h_ln_b, h_W, h_b, out);

    (void)in_sizes; (void)n_in; (void)out_size;
}

// round 5
// speedup vs baseline: 1.9278x; 1.6239x over previous
#include <cuda_runtime.h>
#include <cuda_bf16.h>

// Problem constants (fixed by the dataset)
#define NC  65536   // candidates
#define BSZ 1024    // batch
#define FD  64      // input features
#define DD  512     // model dim
#define DBD 1024    // hidden dim
#define CC  96      // context size

typedef __nv_bfloat16 bf16;

// ---------------- device scratch (allocation-free rule: __device__ globals) ----
// fp32 buffers
__device__ float g_h    [(long)NC*DD];
__device__ float g_k    [(long)NC*DD];
__device__ float g_cproj[(long)NC*DBD];
__device__ float g_cnorm[NC];
__device__ float g_d2   [(long)BSZ*NC];
__device__ float g_hx   [BSZ*DD];
__device__ float g_kx   [BSZ*DD];
__device__ float g_kproj[BSZ*DBD];
__device__ float g_kxn  [BSZ];
__device__ int   g_idx  [BSZ*CC];
__device__ float g_probs[BSZ*CC];
__device__ float g_ybar [BSZ];
__device__ float g_x2   [BSZ*DD];
__device__ float g_x3   [BSZ*DD];

// split bf16 activation buffers (hi/lo)
__device__ bf16 g_candh[(long)NC*FD],  g_candl[(long)NC*FD];
__device__ bf16 g_hh   [(long)NC*DD],  g_hl   [(long)NC*DD];
__device__ bf16 g_th   [(long)NC*DBD], g_tl   [(long)NC*DBD];
__device__ bf16 g_hnh  [(long)NC*DD],  g_hnl  [(long)NC*DD];
__device__ bf16 g_kh   [(long)NC*DD],  g_kl   [(long)NC*DD];
__device__ bf16 g_xh   [BSZ*FD],  g_xl   [BSZ*FD];
__device__ bf16 g_hxh  [BSZ*DD],  g_hxl  [BSZ*DD];
__device__ bf16 g_txh  [BSZ*DBD], g_txl  [BSZ*DBD];
__device__ bf16 g_xnh  [BSZ*DD],  g_xnl  [BSZ*DD];
__device__ bf16 g_kxh  [BSZ*DD],  g_kxl  [BSZ*DD];
__device__ bf16 g_sh   [BSZ*DBD], g_sl   [BSZ*DBD];

// split + transposed weights [N,K]
__device__ bf16 g_wlinh[DD*FD],   g_wlinl[DD*FD];
__device__ bf16 g_we1h [DBD*DD],  g_we1l [DBD*DD];
__device__ bf16 g_we2h [DD*DBD],  g_we2l [DD*DBD];
__device__ bf16 g_wKh  [DD*DD],   g_wKl  [DD*DD];
__device__ bf16 g_wT1h [DBD*DD],  g_wT1l [DBD*DD];
__device__ bf16 g_wT2h [DD*DBD],  g_wT2l [DD*DBD];
__device__ bf16 g_wp1h [DBD*DD],  g_wp1l [DBD*DD];
__device__ bf16 g_wp2h [DD*DBD],  g_wp2l [DD*DBD];

// ---------------- helpers -------------------------------------------------------
__device__ __forceinline__ void split1(float x, bf16 &h, bf16 &l) {
    h = __float2bfloat16_rn(x);
    l = __float2bfloat16_rn(x - __bfloat162float(h));
}

__device__ __forceinline__ void mma_bf16(float c[4], const unsigned a[4], const unsigned b[2]) {
    asm volatile(
        "mma.sync.aligned.m16n8k16.row.col.f32.bf16.bf16.f32 "
        "{%0,%1,%2,%3}, {%4,%5,%6,%7}, {%8,%9}, {%0,%1,%2,%3};"
        : "+f"(c[0]), "+f"(c[1]), "+f"(c[2]), "+f"(c[3])
        : "r"(a[0]), "r"(a[1]), "r"(a[2]), "r"(a[3]), "r"(b[0]), "r"(b[1]));
}

__device__ __forceinline__ void cp16(void* sdst, const void* gsrc) {
    unsigned s = (unsigned)__cvta_generic_to_shared(sdst);
    asm volatile("cp.async.cg.shared.global [%0], [%1], 16;\n" :: "r"(s), "l"(gsrc));
}

__device__ __forceinline__ float blockSum(float v, float* sh) {
    __syncthreads();
    int lane = threadIdx.x & 31, w = threadIdx.x >> 5;
#pragma unroll
    for (int o = 16; o; o >>= 1) v += __shfl_xor_sync(0xffffffffu, v, o);
    if (lane == 0) sh[w] = v;
    __syncthreads();
    if (threadIdx.x == 0) {
        float s = 0.f; int nw = blockDim.x >> 5;
        for (int i = 0; i < nw; i++) s += sh[i];
        sh[32] = s;
    }
    __syncthreads();
    return sh[32];
}

__device__ __forceinline__ float blockMax(float v, float* sh) {
    __syncthreads();
    int lane = threadIdx.x & 31, w = threadIdx.x >> 5;
#pragma unroll
    for (int o = 16; o; o >>= 1) v = fmaxf(v, __shfl_xor_sync(0xffffffffu, v, o));
    if (lane == 0) sh[w] = v;
    __syncthreads();
    if (threadIdx.x == 0) {
        float s = -3.4e38f; int nw = blockDim.x >> 5;
        for (int i = 0; i < nw; i++) s = fmaxf(s, sh[i]);
        sh[32] = s;
    }
    __syncthreads();
    return sh[32];
}

// ---------------- split-bf16 tensor-core GEMM (operands pre-split) -------------
// A: [M,K] hi/lo bf16, row-major k-contiguous. B: [N,K] hi/lo bf16.
// C = A·B^T with 3-term compensation (hh + hl + lh) => ~fp32 accuracy.
// 128x128 block, kTile=16, 2-stage cp.async, 8 warps 2(M)x4(N), mma m16n8k16.
// MODE 0: +bias   MODE 1: relu(+bias)   MODE 2: +bias+res
// MODE 3: rowv[m]+colv[n]-2*AB          MODE 4: AB+res+rowv[m]*bias[n]+colv[n]
// WF32: write fp32 C.  WSPLIT: write split bf16 Chi/Clo.
template<int MODE, bool WF32, bool WSPLIT>
__global__ __launch_bounds__(256) void gemm_bf16s_k(
    int M, int N, int K,
    const bf16* __restrict__ Ahg, const bf16* __restrict__ Alg,
    const bf16* __restrict__ Bhg, const bf16* __restrict__ Blg,
    const float* __restrict__ bias, const float* __restrict__ res,
    const float* __restrict__ rowv, const float* __restrict__ colv,
    float* __restrict__ C, bf16* __restrict__ Chi, bf16* __restrict__ Clo)
{
    __shared__ __align__(16) bf16 Ah[2][128][24];
    __shared__ __align__(16) bf16 Al[2][128][24];
    __shared__ __align__(16) bf16 Bh[2][128][24];
    __shared__ __align__(16) bf16 Bl[2][128][24];

    const int tid  = threadIdx.x;
    const int lane = tid & 31;
    const int wid  = tid >> 5;
    const int wm   = (wid & 1) * 64;
    const int wn   = (wid >> 1) * 32;
    const int grp  = lane >> 2;    // 0..7
    const int thr  = lane & 3;     // 0..3

    const long rowBase = (long)blockIdx.y * 128;
    const long colBase = (long)blockIdx.x * 128;

    const int r   = tid >> 1;          // 0..127
    const int seg = (tid & 1) * 8;     // 0 or 8 (bf16 elems)

    float acc[4][4][4];
#pragma unroll
    for (int mi = 0; mi < 4; mi++)
#pragma unroll
        for (int ni = 0; ni < 4; ni++)
#pragma unroll
            for (int j = 0; j < 4; j++) acc[mi][ni][j] = 0.f;

    const int T = K >> 4;

    // prologue: stage 0
    {
        const long aoff = (rowBase + r) * (long)K + seg;
        const long boff = (colBase + r) * (long)K + seg;
        cp16(&Ah[0][r][seg], Ahg + aoff);
        cp16(&Al[0][r][seg], Alg + aoff);
        cp16(&Bh[0][r][seg], Bhg + boff);
        cp16(&Bl[0][r][seg], Blg + boff);
        asm volatile("cp.async.commit_group;\n" ::);
    }

    for (int t = 0; t < T; t++) {
        const int cur = t & 1, nxt = cur ^ 1;
        if (t + 1 < T) {
            const int k0 = (t + 1) << 4;
            const long aoff = (rowBase + r) * (long)K + k0 + seg;
            const long boff = (colBase + r) * (long)K + k0 + seg;
            cp16(&Ah[nxt][r][seg], Ahg + aoff);
            cp16(&Al[nxt][r][seg], Alg + aoff);
            cp16(&Bh[nxt][r][seg], Bhg + boff);
            cp16(&Bl[nxt][r][seg], Blg + boff);
            asm volatile("cp.async.commit_group;\n" ::);
            asm volatile("cp.async.wait_group 1;\n" ::);
        } else {
            asm volatile("cp.async.wait_group 0;\n" ::);
        }
        __syncthreads();

        {
            unsigned ah[4][4], al[4][4], bh[4][2], bl[4][2];
#pragma unroll
            for (int mi = 0; mi < 4; mi++) {
                int m = wm + mi * 16 + grp;
                ah[mi][0] = *(const unsigned*)&Ah[cur][m][2 * thr];
                ah[mi][1] = *(const unsigned*)&Ah[cur][m + 8][2 * thr];
                ah[mi][2] = *(const unsigned*)&Ah[cur][m][2 * thr + 8];
                ah[mi][3] = *(const unsigned*)&Ah[cur][m + 8][2 * thr + 8];
                al[mi][0] = *(const unsigned*)&Al[cur][m][2 * thr];
                al[mi][1] = *(const unsigned*)&Al[cur][m + 8][2 * thr];
                al[mi][2] = *(const unsigned*)&Al[cur][m][2 * thr + 8];
                al[mi][3] = *(const unsigned*)&Al[cur][m + 8][2 * thr + 8];
            }
#pragma unroll
            for (int ni = 0; ni < 4; ni++) {
                int n = wn + ni * 8 + grp;
                bh[ni][0] = *(const unsigned*)&Bh[cur][n][2 * thr];
                bh[ni][1] = *(const unsigned*)&Bh[cur][n][2 * thr + 8];
                bl[ni][0] = *(const unsigned*)&Bl[cur][n][2 * thr];
                bl[ni][1] = *(const unsigned*)&Bl[cur][n][2 * thr + 8];
            }
#pragma unroll
            for (int mi = 0; mi < 4; mi++)
#pragma unroll
                for (int ni = 0; ni < 4; ni++) {
                    mma_bf16(acc[mi][ni], ah[mi], bh[ni]);
                    mma_bf16(acc[mi][ni], ah[mi], bl[ni]);
                    mma_bf16(acc[mi][ni], al[mi], bh[ni]);
                }
        }
        __syncthreads();
    }

    // ---- epilogue --------------------------------------------------------
#pragma unroll
    for (int mi = 0; mi < 4; mi++) {
#pragma unroll
        for (int half = 0; half < 2; half++) {
            const long rr = rowBase + wm + mi * 16 + grp + half * 8;
            const float rv = (MODE == 3 || MODE == 4) ? rowv[rr] : 0.f;
#pragma unroll
            for (int ni = 0; ni < 4; ni++) {
                const long c = colBase + wn + ni * 8 + thr * 2;
                float o0 = acc[mi][ni][half * 2 + 0];
                float o1 = acc[mi][ni][half * 2 + 1];
                if (MODE == 0 || MODE == 1 || MODE == 2) {
                    if (bias) { o0 += bias[c]; o1 += bias[c + 1]; }
                }
                if (MODE == 2) {
                    o0 += res[rr * N + c]; o1 += res[rr * N + c + 1];
                }
                if (MODE == 1) { o0 = fmaxf(o0, 0.f); o1 = fmaxf(o1, 0.f); }
                if (MODE == 3) {
                    o0 = rv + colv[c]     - 2.f * o0;
                    o1 = rv + colv[c + 1] - 2.f * o1;
                }
                if (MODE == 4) {
                    o0 = o0 + res[rr * N + c]     + rv * bias[c]     + colv[c];
                    o1 = o1 + res[rr * N + c + 1] + rv * bias[c + 1] + colv[c + 1];
                }
                if (WF32)
                    *(float2*)(C + rr * N + c) = make_float2(o0, o1);
                if (WSPLIT) {
                    bf16 h0, l0, h1, l1;
                    split1(o0, h0, l0);
                    split1(o1, h1, l1);
                    ushort2 hp, lp;
                    hp.x = __bfloat16_as_ushort(h0); hp.y = __bfloat16_as_ushort(h1);
                    lp.x = __bfloat16_as_ushort(l0); lp.y = __bfloat16_as_ushort(l1);
                    *(ushort2*)&Chi[rr * N + c] = hp;
                    *(ushort2*)&Clo[rr * N + c] = lp;
                }
            }
        }
    }
}

// ---------------- split fp32 -> bf16 hi/lo (same layout) -----------------------
__global__ void split4_k(const float* __restrict__ in, bf16* __restrict__ oh,
                         bf16* __restrict__ ol, long n)
{
    long i = ((long)blockIdx.x * blockDim.x + threadIdx.x) * 4;
    if (i >= n) return;
    float4 v = *(const float4*)(in + i);
    bf16 h0,l0,h1,l1,h2,l2,h3,l3;
    split1(v.x,h0,l0); split1(v.y,h1,l1); split1(v.z,h2,l2); split1(v.w,h3,l3);
    ushort4 hp, lp;
    hp.x=__bfloat16_as_ushort(h0); hp.y=__bfloat16_as_ushort(h1);
    hp.z=__bfloat16_as_ushort(h2); hp.w=__bfloat16_as_ushort(h3);
    lp.x=__bfloat16_as_ushort(l0); lp.y=__bfloat16_as_ushort(l1);
    lp.z=__bfloat16_as_ushort(l2); lp.w=__bfloat16_as_ushort(l3);
    *(ushort4*)&oh[i] = hp;
    *(ushort4*)&ol[i] = lp;
}

// ---------------- weight split + transpose: [K,N] fp32 -> [N,K] bf16 hi/lo -----
__global__ void wsplitT_k(const float* __restrict__ in, int K, int N,
                          bf16* __restrict__ oh, bf16* __restrict__ ol)
{
    __shared__ float tile[32][33];
    int n0 = blockIdx.x * 32, k0 = blockIdx.y * 32;
    int tx = threadIdx.x, ty = threadIdx.y;   // 32 x 8
#pragma unroll
    for (int j = 0; j < 4; j++)
        tile[ty + j * 8][tx] = in[(long)(k0 + ty + j * 8) * N + n0 + tx];
    __syncthreads();
#pragma unroll
    for (int j = 0; j < 4; j++) {
        float v = tile[tx][ty + j * 8];
        bf16 h, l; split1(v, h, l);
        long o = (long)(n0 + ty + j * 8) * K + k0 + tx;
        oh[o] = h; ol[o] = l;
    }
}

// ---------------- layernorm (width 512) -> split bf16 --------------------------
__global__ void ln512_split_k(const float* __restrict__ in, const float* __restrict__ g,
                              const float* __restrict__ b,
                              bf16* __restrict__ oh, bf16* __restrict__ ol)
{
    __shared__ float sh[33];
    const long row = blockIdx.x;
    const float* x = in + row * DD;
    int t = threadIdx.x;
    float a = x[t], c = x[t + 256];
    float m = blockSum(a + c, sh) * (1.f / DD);
    float d0 = a - m, d1 = c - m;
    float var = blockSum(d0 * d0 + d1 * d1, sh) * (1.f / DD);
    float inv = rsqrtf(var + 1e-5f);
    float o0 = d0 * inv * g[t]       + b[t];
    float o1 = d1 * inv * g[t + 256] + b[t + 256];
    bf16 h, l;
    split1(o0, h, l); oh[row * DD + t] = h;       ol[row * DD + t] = l;
    split1(o1, h, l); oh[row * DD + t + 256] = h; ol[row * DD + t + 256] = l;
}

// ---------------- row squared-norms (width 512) --------------------------------
__global__ void rownorm512_k(const float* __restrict__ in, float* __restrict__ out)
{
    __shared__ float sh[33];
    const long row = blockIdx.x;
    const float* x = in + row * DD;
    int t = threadIdx.x;
    float a = x[t], c = x[t + 256];
    float s = blockSum(a * a + c * c, sh);
    if (t == 0) out[row] = s;
}

// ---------------- top-96 via 8-bit radix select on monotone float keys --------
__device__ __forceinline__ unsigned fkey(float f) {
    unsigned u = __float_as_uint(f);
    return (u & 0x80000000u) ? ~u : (u | 0x80000000u);
}

__global__ void topk96_k(const float* __restrict__ d2, int* __restrict__ idxo)
{
    const int b = blockIdx.x;
    const float* row = d2 + (long)b * NC;
    __shared__ int hist[256];
    __shared__ unsigned s_prefix;
    __shared__ int s_k, s_below;
    const int tid = threadIdx.x;
    if (tid == 0) { s_prefix = 0u; s_k = CC; s_below = 0; }
    __syncthreads();

#pragma unroll
    for (int p = 0; p < 4; p++) {
        const int shift = 24 - p * 8;
        const unsigned pmask = (p == 0) ? 0u : (0xFFFFFFFFu << (shift + 8));
        hist[tid] = 0;
        __syncthreads();
        const unsigned pref = s_prefix;
        for (int i = tid; i < NC; i += 256) {
            unsigned u = fkey(row[i]);
            if ((u & pmask) == pref) atomicAdd(&hist[(u >> shift) & 255], 1);
        }
        __syncthreads();
        if (tid == 0) {
            int cum = 0, kk = s_k;
            for (int bin = 0; bin < 256; bin++) {
                int h = hist[bin];
                if (cum + h >= kk) {
                    s_prefix = pref | ((unsigned)bin << shift);
                    s_k = kk - cum;
                    s_below += cum;
                    break;
                }
                cum += h;
            }
        }
        __syncthreads();
    }
    const unsigned T = s_prefix;
    const int below = s_below;
    __shared__ int cl, ce;
    if (tid == 0) { cl = 0; ce = 0; }
    __syncthreads();
    for (int i = tid; i < NC; i += 256) {
        unsigned u = fkey(row[i]);
        if (u < T) {
            int pos = atomicAdd(&cl, 1);
            idxo[b * CC + pos] = i;
        } else if (u == T) {
            int pos = atomicAdd(&ce, 1);
            if (below + pos < CC) idxo[b * CC + below + pos] = i;
        }
    }
}

// ---------------- softmax over gathered sims + ybar -----------------------------
__global__ void softmax96_k(const float* __restrict__ d2, const int* __restrict__ idx,
                            const float* __restrict__ cy, float* __restrict__ probs,
                            float* __restrict__ ybar)
{
    __shared__ float sh[33];
    const int b = blockIdx.x, t = threadIdx.x;   // 128 threads
    int id = (t < CC) ? idx[b * CC + t] : 0;
    float sim = (t < CC) ? -d2[(long)b * NC + id] : -3.4e38f;
    float mx = blockMax(sim, sh);
    float e = (t < CC) ? expf(sim - mx) : 0.f;
    float s = blockSum(e, sh);
    float p = e / s;
    if (t < CC) probs[b * CC + t] = p;
    float yv = (t < CC) ? p * cy[id] : 0.f;
    float yb = blockSum(yv, sh);
    if (t == 0) ybar[b] = yb;
}

// ---------- s[b,:] = sum_c probs * relu(kproj - cproj[idx]), split output -------
__global__ void ctxsum_split_k(const float* __restrict__ kproj, const float* __restrict__ cproj,
                               const int* __restrict__ idx, const float* __restrict__ probs,
                               bf16* __restrict__ oh, bf16* __restrict__ ol)
{
    const int b = blockIdx.x, j = threadIdx.x;   // 1024 threads
    __shared__ int   si[CC];
    __shared__ float sp[CC];
    if (j < CC) { si[j] = idx[b * CC + j]; sp[j] = probs[b * CC + j]; }
    __syncthreads();
    float kp = kproj[(long)b * DBD + j];
    float acc = 0.f;
#pragma unroll 4
    for (int c = 0; c < CC; c++) {
        float v = kp - cproj[(long)si[c] * DBD + j];
        acc += sp[c] * fmaxf(v, 0.f);
    }
    bf16 h, l; split1(acc, h, l);
    oh[(long)b * DBD + j] = h;
    ol[(long)b * DBD + j] = l;
}

// ---------------- head: relu(ln(x)) @ h_W + h_b ---------------------------------
__global__ void head512_k(const float* __restrict__ in, const float* __restrict__ g,
                          const float* __restrict__ bb, const float* __restrict__ hW,
                          const float* __restrict__ hb, float* __restrict__ out)
{
    __shared__ float sh[33];
    const long row = blockIdx.x;
    const float* x = in + row * DD;
    int t = threadIdx.x;
    float a = x[t], c = x[t + 256];
    float m = blockSum(a + c, sh) * (1.f / DD);
    float d0 = a - m, d1 = c - m;
    float v = blockSum(d0 * d0 + d1 * d1, sh) * (1.f / DD);
    float inv = rsqrtf(v + 1e-5f);
    float s0 = fmaxf(d0 * inv * g[t] + bb[t], 0.f) * hW[t];
    float s1 = fmaxf(d1 * inv * g[t + 256] + bb[t + 256], 0.f) * hW[t + 256];
    float tot = blockSum(s0 + s1, sh);
    if (t == 0) out[row] = tot + hb[0];
}

// ---------------- host side -----------------------------------------------------
template<typename T>
static T* devptr(const void* sym) {
    void* p = nullptr;
    cudaGetSymbolAddress(&p, sym);
    return (T*)p;
}

template<int MODE, bool WF32, bool WSPLIT>
static void launch_gemm(int M, int N, int K,
                        const bf16* Ah, const bf16* Al, const bf16* Bh, const bf16* Bl,
                        const float* bias, const float* res,
                        const float* rowv, const float* colv,
                        float* C, bf16* Chi, bf16* Clo) {
    dim3 grid(N / 128, M / 128);
    gemm_bf16s_k<MODE, WF32, WSPLIT><<<grid, 256>>>(M, N, K, Ah, Al, Bh, Bl,
                                                    bias, res, rowv, colv, C, Chi, Clo);
}

extern "C" void kernel_launch(void* const* d_in, const int* in_sizes, int n_in,
                              void* d_out, int out_size)
{
    const float* x_num  = (const float*)d_in[0];
    const float* cand   = (const float*)d_in[1];
    const float* cy     = (const float*)d_in[2];
    const float* lin_W  = (const float*)d_in[3];
    const float* lin_b  = (const float*)d_in[4];
    const float* e_W1   = (const float*)d_in[5];
    const float* e_b1   = (const float*)d_in[6];
    const float* e_W2   = (const float*)d_in[7];
    const float* e_b2   = (const float*)d_in[8];
    const float* mix_g  = (const float*)d_in[9];
    const float* mix_b  = (const float*)d_in[10];
    const float* K_W    = (const float*)d_in[11];
    const float* K_b    = (const float*)d_in[12];
    const float* lab_W  = (const float*)d_in[13];
    const float* lab_b  = (const float*)d_in[14];
    const float* T_W1   = (const float*)d_in[15];
    const float* T_b1   = (const float*)d_in[16];
    const float* T_W2   = (const float*)d_in[17];
    const float* p_ln_g = (const float*)d_in[18];
    const float* p_ln_b = (const float*)d_in[19];
    const float* p_W1   = (const float*)d_in[20];
    const float* p_b1   = (const float*)d_in[21];
    const float* p_W2   = (const float*)d_in[22];
    const float* p_b2   = (const float*)d_in[23];
    const float* h_ln_g = (const float*)d_in[24];
    const float* h_ln_b = (const float*)d_in[25];
    const float* h_W    = (const float*)d_in[26];
    const float* h_b    = (const float*)d_in[27];
    float* out = (float*)d_out;

    float* p_h     = devptr<float>(g_h);
    float* p_k     = devptr<float>(g_k);
    float* p_cproj = devptr<float>(g_cproj);
    float* p_cnorm = devptr<float>(g_cnorm);
    float* p_d2    = devptr<float>(g_d2);
    float* p_hx    = devptr<float>(g_hx);
    float* p_kx    = devptr<float>(g_kx);
    float* p_kproj = devptr<float>(g_kproj);
    float* p_kxn   = devptr<float>(g_kxn);
    int*   p_idx   = devptr<int>(g_idx);
    float* p_probs = devptr<float>(g_probs);
    float* p_ybar  = devptr<float>(g_ybar);
    float* p_x2    = devptr<float>(g_x2);
    float* p_x3    = devptr<float>(g_x3);

    bf16 *candh = devptr<bf16>(g_candh), *candl = devptr<bf16>(g_candl);
    bf16 *hh = devptr<bf16>(g_hh),   *hl = devptr<bf16>(g_hl);
    bf16 *th = devptr<bf16>(g_th),   *tl = devptr<bf16>(g_tl);
    bf16 *hnh = devptr<bf16>(g_hnh), *hnl = devptr<bf16>(g_hnl);
    bf16 *kh = devptr<bf16>(g_kh),   *kl = devptr<bf16>(g_kl);
    bf16 *xh = devptr<bf16>(g_xh),   *xl = devptr<bf16>(g_xl);
    bf16 *hxh = devptr<bf16>(g_hxh), *hxl = devptr<bf16>(g_hxl);
    bf16 *txh = devptr<bf16>(g_txh), *txl = devptr<bf16>(g_txl);
    bf16 *xnh = devptr<bf16>(g_xnh), *xnl = devptr<bf16>(g_xnl);
    bf16 *kxh = devptr<bf16>(g_kxh), *kxl = devptr<bf16>(g_kxl);
    bf16 *sh_ = devptr<bf16>(g_sh),  *sl_ = devptr<bf16>(g_sl);

    bf16 *wlinh = devptr<bf16>(g_wlinh), *wlinl = devptr<bf16>(g_wlinl);
    bf16 *we1h = devptr<bf16>(g_we1h),   *we1l = devptr<bf16>(g_we1l);
    bf16 *we2h = devptr<bf16>(g_we2h),   *we2l = devptr<bf16>(g_we2l);
    bf16 *wKh = devptr<bf16>(g_wKh),     *wKl = devptr<bf16>(g_wKl);
    bf16 *wT1h = devptr<bf16>(g_wT1h),   *wT1l = devptr<bf16>(g_wT1l);
    bf16 *wT2h = devptr<bf16>(g_wT2h),   *wT2l = devptr<bf16>(g_wT2l);
    bf16 *wp1h = devptr<bf16>(g_wp1h),   *wp1l = devptr<bf16>(g_wp1l);
    bf16 *wp2h = devptr<bf16>(g_wp2h),   *wp2l = devptr<bf16>(g_wp2l);

    // ---- one-time prep: split inputs + split/transpose weights --------------
    split4_k<<<(NC * FD / 4 + 255) / 256, 256>>>(cand, candh, candl, (long)NC * FD);
    split4_k<<<(BSZ * FD / 4 + 255) / 256, 256>>>(x_num, xh, xl, (long)BSZ * FD);
    {
        dim3 blk(32, 8);
        wsplitT_k<<<dim3(DD / 32, FD / 32), blk>>>(lin_W, FD, DD, wlinh, wlinl);
        wsplitT_k<<<dim3(DBD / 32, DD / 32), blk>>>(e_W1, DD, DBD, we1h, we1l);
        wsplitT_k<<<dim3(DD / 32, DBD / 32), blk>>>(e_W2, DBD, DD, we2h, we2l);
        wsplitT_k<<<dim3(DD / 32, DD / 32), blk>>>(K_W, DD, DD, wKh, wKl);
        wsplitT_k<<<dim3(DBD / 32, DD / 32), blk>>>(T_W1, DD, DBD, wT1h, wT1l);
        wsplitT_k<<<dim3(DD / 32, DBD / 32), blk>>>(T_W2, DBD, DD, wT2h, wT2l);
        wsplitT_k<<<dim3(DBD / 32, DD / 32), blk>>>(p_W1, DD, DBD, wp1h, wp1l);
        wsplitT_k<<<dim3(DD / 32, DBD / 32), blk>>>(p_W2, DBD, DD, wp2h, wp2l);
    }

    // ---- candidate encoder -----------------------------------------------
    launch_gemm<0, true, true>(NC, DD, FD, candh, candl, wlinh, wlinl,
                               lin_b, nullptr, nullptr, nullptr, p_h, hh, hl);
    launch_gemm<1, false, true>(NC, DBD, DD, hh, hl, we1h, we1l,
                                e_b1, nullptr, nullptr, nullptr, nullptr, th, tl);
    launch_gemm<2, true, false>(NC, DD, DBD, th, tl, we2h, we2l,
                                e_b2, p_h, nullptr, nullptr, p_h, nullptr, nullptr);
    ln512_split_k<<<NC, 256>>>(p_h, mix_g, mix_b, hnh, hnl);
    launch_gemm<0, true, true>(NC, DD, DD, hnh, hnl, wKh, wKl,
                               K_b, nullptr, nullptr, nullptr, p_k, kh, kl);
    launch_gemm<0, true, false>(NC, DBD, DD, kh, kl, wT1h, wT1l,
                                nullptr, nullptr, nullptr, nullptr, p_cproj, nullptr, nullptr);
    rownorm512_k<<<NC, 256>>>(p_k, p_cnorm);

    // ---- query encoder ----------------------------------------------------
    launch_gemm<0, true, true>(BSZ, DD, FD, xh, xl, wlinh, wlinl,
                               lin_b, nullptr, nullptr, nullptr, p_hx, hxh, hxl);
    launch_gemm<1, false, true>(BSZ, DBD, DD, hxh, hxl, we1h, we1l,
                                e_b1, nullptr, nullptr, nullptr, nullptr, txh, txl);
    launch_gemm<2, true, false>(BSZ, DD, DBD, txh, txl, we2h, we2l,
                                e_b2, p_hx, nullptr, nullptr, p_hx, nullptr, nullptr);
    ln512_split_k<<<BSZ, 256>>>(p_hx, mix_g, mix_b, xnh, xnl);
    launch_gemm<0, true, true>(BSZ, DD, DD, xnh, xnl, wKh, wKl,
                               K_b, nullptr, nullptr, nullptr, p_kx, kxh, kxl);
    launch_gemm<0, true, false>(BSZ, DBD, DD, kxh, kxl, wT1h, wT1l,
                                T_b1, nullptr, nullptr, nullptr, p_kproj, nullptr, nullptr);
    rownorm512_k<<<BSZ, 256>>>(p_kx, p_kxn);

    // ---- kNN scores + top-96 ----------------------------------------------
    launch_gemm<3, true, false>(BSZ, NC, DD, kxh, kxl, kh, kl,
                                nullptr, nullptr, p_kxn, p_cnorm, p_d2, nullptr, nullptr);
    topk96_k<<<BSZ, 256>>>(p_d2, p_idx);
    softmax96_k<<<BSZ, 128>>>(p_d2, p_idx, cy, p_probs, p_ybar);

    // ---- context aggregation ----------------------------------------------
    ctxsum_split_k<<<BSZ, 1024>>>(p_kproj, p_cproj, p_idx, p_probs, sh_, sl_);
    launch_gemm<4, true, false>(BSZ, DD, DBD, sh_, sl_, wT2h, wT2l,
                                lab_W, p_hx, p_ybar, lab_b, p_x2, nullptr, nullptr);

    // ---- predictor block + head -------------------------------------------
    ln512_split_k<<<BSZ, 256>>>(p_x2, p_ln_g, p_ln_b, xnh, xnl);
    launch_gemm<1, false, true>(BSZ, DBD, DD, xnh, xnl, wp1h, wp1l,
                                p_b1, nullptr, nullptr, nullptr, nullptr, txh, txl);
    launch_gemm<2, true, false>(BSZ, DD, DBD, txh, txl, wp2h, wp2l,
                                p_b2, p_x2, nullptr, nullptr, p_x3, nullptr, nullptr);
    head512_k<<<BSZ, 256>>>(p_x3, h_ln_g, h_ln_b, h_W, h_b, out);

    (void)in_sizes; (void)n_in; (void)out_size;
}

// round 7
// speedup vs baseline: 2.5157x; 1.3050x over previous
#include <cuda_runtime.h>
#include <cuda_bf16.h>
#include <cstdint>

// Problem constants (fixed by the dataset)
#define NC  65536   // candidates
#define BSZ 1024    // batch
#define FD  64      // input features
#define DD  512     // model dim
#define DBD 1024    // hidden dim
#define CC  96      // context size

typedef __nv_bfloat16 bf16;

// ---------------- device scratch (allocation-free rule: __device__ globals) ----
__device__ float g_h    [(long)NC*DD];
__device__ float g_k    [(long)NC*DD];
__device__ float g_cproj[(long)NC*DBD];
__device__ float g_cnorm[NC];
__device__ float g_d2   [(long)BSZ*NC];
__device__ float g_hx   [BSZ*DD];
__device__ float g_kx   [BSZ*DD];
__device__ float g_kproj[BSZ*DBD];
__device__ float g_kxn  [BSZ];
__device__ int   g_idx  [BSZ*CC];
__device__ float g_probs[BSZ*CC];
__device__ float g_ybar [BSZ];
__device__ float g_x2   [BSZ*DD];
__device__ float g_x3   [BSZ*DD];

// split bf16 activation buffers (hi/lo)
__device__ bf16 g_candh[(long)NC*FD],  g_candl[(long)NC*FD];
__device__ bf16 g_hh   [(long)NC*DD],  g_hl   [(long)NC*DD];
__device__ bf16 g_th   [(long)NC*DBD], g_tl   [(long)NC*DBD];
__device__ bf16 g_hnh  [(long)NC*DD],  g_hnl  [(long)NC*DD];
__device__ bf16 g_kh   [(long)NC*DD],  g_kl   [(long)NC*DD];
__device__ bf16 g_xh   [BSZ*FD],  g_xl   [BSZ*FD];
__device__ bf16 g_hxh  [BSZ*DD],  g_hxl  [BSZ*DD];
__device__ bf16 g_txh  [BSZ*DBD], g_txl  [BSZ*DBD];
__device__ bf16 g_xnh  [BSZ*DD],  g_xnl  [BSZ*DD];
__device__ bf16 g_kxh  [BSZ*DD],  g_kxl  [BSZ*DD];
__device__ bf16 g_sh   [BSZ*DBD], g_sl   [BSZ*DBD];

// split + transposed weights [N,K]
__device__ bf16 g_wlinh[DD*FD],   g_wlinl[DD*FD];
__device__ bf16 g_we1h [DBD*DD],  g_we1l [DBD*DD];
__device__ bf16 g_we2h [DD*DBD],  g_we2l [DD*DBD];
__device__ bf16 g_wKh  [DD*DD],   g_wKl  [DD*DD];
__device__ bf16 g_wT1h [DBD*DD],  g_wT1l [DBD*DD];
__device__ bf16 g_wT2h [DD*DBD],  g_wT2l [DD*DBD];
__device__ bf16 g_wp1h [DBD*DD],  g_wp1l [DBD*DD];
__device__ bf16 g_wp2h [DD*DBD],  g_wp2l [DD*DBD];

// ---------------- helpers -------------------------------------------------------
__device__ __forceinline__ void split1(float x, bf16 &h, bf16 &l) {
    h = __float2bfloat16_rn(x);
    l = __float2bfloat16_rn(x - __bfloat162float(h));
}

__device__ __forceinline__ void mma_bf16(float c[4], const unsigned a[4], const unsigned b[2]) {
    asm volatile(
        "mma.sync.aligned.m16n8k16.row.col.f32.bf16.bf16.f32 "
        "{%0,%1,%2,%3}, {%4,%5,%6,%7}, {%8,%9}, {%0,%1,%2,%3};"
        : "+f"(c[0]), "+f"(c[1]), "+f"(c[2]), "+f"(c[3])
        : "r"(a[0]), "r"(a[1]), "r"(a[2]), "r"(a[3]), "r"(b[0]), "r"(b[1]));
}

__device__ __forceinline__ void cp16s(unsigned saddr, const void* gsrc) {
    asm volatile("cp.async.cg.shared.global [%0], [%1], 16;\n" :: "r"(saddr), "l"(gsrc));
}

__device__ __forceinline__ void ldsm4(unsigned &r0, unsigned &r1, unsigned &r2,
                                      unsigned &r3, unsigned addr) {
    asm volatile("ldmatrix.sync.aligned.m8n8.x4.shared.b16 {%0,%1,%2,%3}, [%4];"
                 : "=r"(r0), "=r"(r1), "=r"(r2), "=r"(r3) : "r"(addr));
}

__device__ __forceinline__ float blockSum(float v, float* sh) {
    __syncthreads();
    int lane = threadIdx.x & 31, w = threadIdx.x >> 5;
#pragma unroll
    for (int o = 16; o; o >>= 1) v += __shfl_xor_sync(0xffffffffu, v, o);
    if (lane == 0) sh[w] = v;
    __syncthreads();
    if (threadIdx.x == 0) {
        float s = 0.f; int nw = blockDim.x >> 5;
        for (int i = 0; i < nw; i++) s += sh[i];
        sh[32] = s;
    }
    __syncthreads();
    return sh[32];
}

__device__ __forceinline__ float blockMax(float v, float* sh) {
    __syncthreads();
    int lane = threadIdx.x & 31, w = threadIdx.x >> 5;
#pragma unroll
    for (int o = 16; o; o >>= 1) v = fmaxf(v, __shfl_xor_sync(0xffffffffu, v, o));
    if (lane == 0) sh[w] = v;
    __syncthreads();
    if (threadIdx.x == 0) {
        float s = -3.4e38f; int nw = blockDim.x >> 5;
        for (int i = 0; i < nw; i++) s = fmaxf(s, sh[i]);
        sh[32] = s;
    }
    __syncthreads();
    return sh[32];
}

// ---------------- split-bf16 tensor-core GEMM (ldmatrix + 3-stage cp.async) ----
// A: [M,K] hi/lo bf16 k-contiguous; B: [N,K] hi/lo bf16. C = A·B^T, 3-term
// compensated (hh + hl + lh), fp32 accumulation.
// Block 128x128, K-chunk 32, 3 stages, 8 warps 2(M)x4(N), mma m16n8k16.
// SMEM: 64B rows, SW64 swizzle -> conflict-free ldmatrix.
// MODE 0: +bias   MODE 1: relu(+bias)   MODE 2: +bias+res
// MODE 3: rowv[m]+colv[n]-2*AB          MODE 4: AB+res+rowv[m]*bias[n]+colv[n]
#define GS_STAGE 32768                   // 4 buffers x 8KB
#define GS_SMEM  (3 * GS_STAGE)

template<int MODE, bool WF32, bool WSPLIT>
__global__ void __launch_bounds__(256, 2) gemm_bf16s_k(
    int M, int N, int K,
    const bf16* __restrict__ Ahg, const bf16* __restrict__ Alg,
    const bf16* __restrict__ Bhg, const bf16* __restrict__ Blg,
    const float* __restrict__ bias, const float* __restrict__ res,
    const float* __restrict__ rowv, const float* __restrict__ colv,
    float* __restrict__ C, bf16* __restrict__ Chi, bf16* __restrict__ Clo)
{
    extern __shared__ __align__(1024) char smem[];
    const unsigned sbase = (unsigned)__cvta_generic_to_shared(smem);

    const int tid  = threadIdx.x;
    const int lane = tid & 31;
    const int wid  = tid >> 5;
    const int wm   = (wid & 1) * 64;
    const int wn   = (wid >> 1) * 32;
    const int grp  = lane >> 2;
    const int thr  = lane & 3;

    const long rowBase = (long)blockIdx.y * 128;
    const long colBase = (long)blockIdx.x * 128;

    float acc[4][4][4];
#pragma unroll
    for (int mi = 0; mi < 4; mi++)
#pragma unroll
        for (int ni = 0; ni < 4; ni++)
#pragma unroll
            for (int j = 0; j < 4; j++) acc[mi][ni][j] = 0.f;

    const int T = K >> 5;    // 32-elem chunks

    // ---- stage fill: chunk t into stage s ---------------------------------
    auto fill = [&](int s, int t) {
        const int k0 = t << 5;
        const unsigned sb = sbase + (unsigned)s * GS_STAGE;
#pragma unroll
        for (int i = 0; i < 2; i++) {
            int q = tid + i * 256;
            int r = q >> 2, c = q & 3;
            int off = r * 64 + c * 16;
            int sw  = off ^ ((off >> 3) & 0x30);
            const long ao = (rowBase + r) * (long)K + k0 + c * 8;
            const long bo = (colBase + r) * (long)K + k0 + c * 8;
            cp16s(sb + sw,          Ahg + ao);
            cp16s(sb + 8192 + sw,   Alg + ao);
            cp16s(sb + 16384 + sw,  Bhg + bo);
            cp16s(sb + 24576 + sw,  Blg + bo);
        }
        asm volatile("cp.async.commit_group;" ::: "memory");
    };

    // lane-derived ldmatrix address components
    const int aRow16 = lane & 15;                   // m offset within 16
    const int aKx    = (lane & 16) ? 16 : 0;        // byte offset (k +8 elems)
    const int bRowO  = (lane & 7) + ((lane & 16) ? 8 : 0);
    const int bKx    = (lane & 8) ? 16 : 0;

    fill(0, 0);
    if (T > 1) fill(1, 1);

    for (int t = 0; t < T; t++) {
        if (t < T - 1) asm volatile("cp.async.wait_group 1;" ::: "memory");
        else           asm volatile("cp.async.wait_group 0;" ::: "memory");
        __syncthreads();
        if (t + 2 < T) fill((t + 2) % 3, t + 2);

        const unsigned ab  = sbase + (unsigned)(t % 3) * GS_STAGE;
        const unsigned alb = ab + 8192, bb = ab + 16384, blb = ab + 24576;

#pragma unroll
        for (int s16 = 0; s16 < 64; s16 += 32) {      // two k16 sub-steps (bytes)
            unsigned ah[4][4], al[4][4];
#pragma unroll
            for (int mi = 0; mi < 4; mi++) {
                int rowb = (wm + mi * 16 + aRow16) * 64;
                unsigned msk = (unsigned)((rowb >> 3) & 0x30);
                ldsm4(ah[mi][0], ah[mi][1], ah[mi][2], ah[mi][3],
                      (ab + rowb + s16 + aKx) ^ msk);
                ldsm4(al[mi][0], al[mi][1], al[mi][2], al[mi][3],
                      (alb + rowb + s16 + aKx) ^ msk);
            }
#pragma unroll
            for (int p = 0; p < 2; p++) {
                int rowb = (wn + p * 16 + bRowO) * 64;
                unsigned msk = (unsigned)((rowb >> 3) & 0x30);
                unsigned bh[4], bl[4];
                ldsm4(bh[0], bh[1], bh[2], bh[3], (bb + rowb + s16 + bKx) ^ msk);
                ldsm4(bl[0], bl[1], bl[2], bl[3], (blb + rowb + s16 + bKx) ^ msk);
#pragma unroll
                for (int mi = 0; mi < 4; mi++) {
                    mma_bf16(acc[mi][2 * p],     ah[mi], &bh[0]);
                    mma_bf16(acc[mi][2 * p],     ah[mi], &bl[0]);
                    mma_bf16(acc[mi][2 * p],     al[mi], &bh[0]);
                    mma_bf16(acc[mi][2 * p + 1], ah[mi], &bh[2]);
                    mma_bf16(acc[mi][2 * p + 1], ah[mi], &bl[2]);
                    mma_bf16(acc[mi][2 * p + 1], al[mi], &bh[2]);
                }
            }
        }
        __syncthreads();
    }

    // ---- epilogue ----------------------------------------------------------
#pragma unroll
    for (int mi = 0; mi < 4; mi++) {
#pragma unroll
        for (int half = 0; half < 2; half++) {
            const long rr = rowBase + wm + mi * 16 + grp + half * 8;
            const float rv = (MODE == 3 || MODE == 4) ? rowv[rr] : 0.f;
#pragma unroll
            for (int ni = 0; ni < 4; ni++) {
                const long c = colBase + wn + ni * 8 + thr * 2;
                float o0 = acc[mi][ni][half * 2 + 0];
                float o1 = acc[mi][ni][half * 2 + 1];
                if (MODE == 0 || MODE == 1 || MODE == 2) {
                    if (bias) { o0 += bias[c]; o1 += bias[c + 1]; }
                }
                if (MODE == 2) {
                    o0 += res[rr * N + c]; o1 += res[rr * N + c + 1];
                }
                if (MODE == 1) { o0 = fmaxf(o0, 0.f); o1 = fmaxf(o1, 0.f); }
                if (MODE == 3) {
                    o0 = rv + colv[c]     - 2.f * o0;
                    o1 = rv + colv[c + 1] - 2.f * o1;
                }
                if (MODE == 4) {
                    o0 = o0 + res[rr * N + c]     + rv * bias[c]     + colv[c];
                    o1 = o1 + res[rr * N + c + 1] + rv * bias[c + 1] + colv[c + 1];
                }
                if (WF32)
                    *(float2*)(C + rr * N + c) = make_float2(o0, o1);
                if (WSPLIT) {
                    bf16 h0, l0, h1, l1;
                    split1(o0, h0, l0);
                    split1(o1, h1, l1);
                    ushort2 hp, lp;
                    hp.x = __bfloat16_as_ushort(h0); hp.y = __bfloat16_as_ushort(h1);
                    lp.x = __bfloat16_as_ushort(l0); lp.y = __bfloat16_as_ushort(l1);
                    *(ushort2*)&Chi[rr * N + c] = hp;
                    *(ushort2*)&Clo[rr * N + c] = lp;
                }
            }
        }
    }
}

// ---------------- split fp32 -> bf16 hi/lo (same layout) -----------------------
__global__ void split4_k(const float* __restrict__ in, bf16* __restrict__ oh,
                         bf16* __restrict__ ol, long n)
{
    long i = ((long)blockIdx.x * blockDim.x + threadIdx.x) * 4;
    if (i >= n) return;
    float4 v = *(const float4*)(in + i);
    bf16 h0,l0,h1,l1,h2,l2,h3,l3;
    split1(v.x,h0,l0); split1(v.y,h1,l1); split1(v.z,h2,l2); split1(v.w,h3,l3);
    ushort4 hp, lp;
    hp.x=__bfloat16_as_ushort(h0); hp.y=__bfloat16_as_ushort(h1);
    hp.z=__bfloat16_as_ushort(h2); hp.w=__bfloat16_as_ushort(h3);
    lp.x=__bfloat16_as_ushort(l0); lp.y=__bfloat16_as_ushort(l1);
    lp.z=__bfloat16_as_ushort(l2); lp.w=__bfloat16_as_ushort(l3);
    *(ushort4*)&oh[i] = hp;
    *(ushort4*)&ol[i] = lp;
}

// ---------------- weight split + transpose: [K,N] fp32 -> [N,K] bf16 hi/lo -----
__global__ void wsplitT_k(const float* __restrict__ in, int K, int N,
                          bf16* __restrict__ oh, bf16* __restrict__ ol)
{
    __shared__ float tile[32][33];
    int n0 = blockIdx.x * 32, k0 = blockIdx.y * 32;
    int tx = threadIdx.x, ty = threadIdx.y;   // 32 x 8
#pragma unroll
    for (int j = 0; j < 4; j++)
        tile[ty + j * 8][tx] = in[(long)(k0 + ty + j * 8) * N + n0 + tx];
    __syncthreads();
#pragma unroll
    for (int j = 0; j < 4; j++) {
        float v = tile[tx][ty + j * 8];
        bf16 h, l; split1(v, h, l);
        long o = (long)(n0 + ty + j * 8) * K + k0 + tx;
        oh[o] = h; ol[o] = l;
    }
}

// ---------------- layernorm (width 512) -> split bf16 --------------------------
__global__ void ln512_split_k(const float* __restrict__ in, const float* __restrict__ g,
                              const float* __restrict__ b,
                              bf16* __restrict__ oh, bf16* __restrict__ ol)
{
    __shared__ float sh[33];
    const long row = blockIdx.x;
    const float* x = in + row * DD;
    int t = threadIdx.x;
    float a = x[t], c = x[t + 256];
    float m = blockSum(a + c, sh) * (1.f / DD);
    float d0 = a - m, d1 = c - m;
    float var = blockSum(d0 * d0 + d1 * d1, sh) * (1.f / DD);
    float inv = rsqrtf(var + 1e-5f);
    float o0 = d0 * inv * g[t]       + b[t];
    float o1 = d1 * inv * g[t + 256] + b[t + 256];
    bf16 h, l;
    split1(o0, h, l); oh[row * DD + t] = h;       ol[row * DD + t] = l;
    split1(o1, h, l); oh[row * DD + t + 256] = h; ol[row * DD + t + 256] = l;
}

// ---------------- row squared-norms (width 512) --------------------------------
__global__ void rownorm512_k(const float* __restrict__ in, float* __restrict__ out)
{
    __shared__ float sh[33];
    const long row = blockIdx.x;
    const float* x = in + row * DD;
    int t = threadIdx.x;
    float a = x[t], c = x[t + 256];
    float s = blockSum(a * a + c * c, sh);
    if (t == 0) out[row] = s;
}

// ---------------- top-96 via 8-bit radix select on monotone float keys --------
__device__ __forceinline__ unsigned fkey(float f) {
    unsigned u = __float_as_uint(f);
    return (u & 0x80000000u) ? ~u : (u | 0x80000000u);
}

__global__ void topk96_k(const float* __restrict__ d2, int* __restrict__ idxo)
{
    const int b = blockIdx.x;
    const float* row = d2 + (long)b * NC;
    __shared__ int hist[256];
    __shared__ unsigned s_prefix;
    __shared__ int s_k, s_below;
    const int tid = threadIdx.x;
    if (tid == 0) { s_prefix = 0u; s_k = CC; s_below = 0; }
    __syncthreads();

#pragma unroll
    for (int p = 0; p < 4; p++) {
        const int shift = 24 - p * 8;
        const unsigned pmask = (p == 0) ? 0u : (0xFFFFFFFFu << (shift + 8));
        hist[tid] = 0;
        __syncthreads();
        const unsigned pref = s_prefix;
        for (int i = tid; i < NC; i += 256) {
            unsigned u = fkey(row[i]);
            if ((u & pmask) == pref) atomicAdd(&hist[(u >> shift) & 255], 1);
        }
        __syncthreads();
        if (tid == 0) {
            int cum = 0, kk = s_k;
            for (int bin = 0; bin < 256; bin++) {
                int h = hist[bin];
                if (cum + h >= kk) {
                    s_prefix = pref | ((unsigned)bin << shift);
                    s_k = kk - cum;
                    s_below += cum;
                    break;
                }
                cum += h;
            }
        }
        __syncthreads();
    }
    const unsigned T = s_prefix;
    const int below = s_below;
    __shared__ int cl, ce;
    if (tid == 0) { cl = 0; ce = 0; }
    __syncthreads();
    for (int i = tid; i < NC; i += 256) {
        unsigned u = fkey(row[i]);
        if (u < T) {
            int pos = atomicAdd(&cl, 1);
            idxo[b * CC + pos] = i;
        } else if (u == T) {
            int pos = atomicAdd(&ce, 1);
            if (below + pos < CC) idxo[b * CC + below + pos] = i;
        }
    }
}

// ---------------- softmax over gathered sims + ybar -----------------------------
__global__ void softmax96_k(const float* __restrict__ d2, const int* __restrict__ idx,
                            const float* __restrict__ cy, float* __restrict__ probs,
                            float* __restrict__ ybar)
{
    __shared__ float sh[33];
    const int b = blockIdx.x, t = threadIdx.x;   // 128 threads
    int id = (t < CC) ? idx[b * CC + t] : 0;
    float sim = (t < CC) ? -d2[(long)b * NC + id] : -3.4e38f;
    float mx = blockMax(sim, sh);
    float e = (t < CC) ? expf(sim - mx) : 0.f;
    float s = blockSum(e, sh);
    float p = e / s;
    if (t < CC) probs[b * CC + t] = p;
    float yv = (t < CC) ? p * cy[id] : 0.f;
    float yb = blockSum(yv, sh);
    if (t == 0) ybar[b] = yb;
}

// ---------- s[b,:] = sum_c probs * relu(kproj - cproj[idx]), split output -------
__global__ void ctxsum_split_k(const float* __restrict__ kproj, const float* __restrict__ cproj,
                               const int* __restrict__ idx, const float* __restrict__ probs,
                               bf16* __restrict__ oh, bf16* __restrict__ ol)
{
    const int b = blockIdx.x, j = threadIdx.x;   // 1024 threads
    __shared__ int   si[CC];
    __shared__ float sp[CC];
    if (j < CC) { si[j] = idx[b * CC + j]; sp[j] = probs[b * CC + j]; }
    __syncthreads();
    float kp = kproj[(long)b * DBD + j];
    float acc = 0.f;
#pragma unroll 4
    for (int c = 0; c < CC; c++) {
        float v = kp - cproj[(long)si[c] * DBD + j];
        acc += sp[c] * fmaxf(v, 0.f);
    }
    bf16 h, l; split1(acc, h, l);
    oh[(long)b * DBD + j] = h;
    ol[(long)b * DBD + j] = l;
}

// ---------------- head: relu(ln(x)) @ h_W + h_b ---------------------------------
__global__ void head512_k(const float* __restrict__ in, const float* __restrict__ g,
                          const float* __restrict__ bb, const float* __restrict__ hW,
                          const float* __restrict__ hb, float* __restrict__ out)
{
    __shared__ float sh[33];
    const long row = blockIdx.x;
    const float* x = in + row * DD;
    int t = threadIdx.x;
    float a = x[t], c = x[t + 256];
    float m = blockSum(a + c, sh) * (1.f / DD);
    float d0 = a - m, d1 = c - m;
    float v = blockSum(d0 * d0 + d1 * d1, sh) * (1.f / DD);
    float inv = rsqrtf(v + 1e-5f);
    float s0 = fmaxf(d0 * inv * g[t] + bb[t], 0.f) * hW[t];
    float s1 = fmaxf(d1 * inv * g[t + 256] + bb[t + 256], 0.f) * hW[t + 256];
    float tot = blockSum(s0 + s1, sh);
    if (t == 0) out[row] = tot + hb[0];
}

// ---------------- host side -----------------------------------------------------
template<typename T>
static T* devptr(const void* sym) {
    void* p = nullptr;
    cudaGetSymbolAddress(&p, sym);
    return (T*)p;
}

template<int MODE, bool WF32, bool WSPLIT>
static void launch_gemm(int M, int N, int K,
                        const bf16* Ah, const bf16* Al, const bf16* Bh, const bf16* Bl,
                        const float* bias, const float* res,
                        const float* rowv, const float* colv,
                        float* C, bf16* Chi, bf16* Clo) {
    cudaFuncSetAttribute(gemm_bf16s_k<MODE, WF32, WSPLIT>,
                         cudaFuncAttributeMaxDynamicSharedMemorySize, GS_SMEM);
    dim3 grid(N / 128, M / 128);
    gemm_bf16s_k<MODE, WF32, WSPLIT><<<grid, 256, GS_SMEM>>>(
        M, N, K, Ah, Al, Bh, Bl, bias, res, rowv, colv, C, Chi, Clo);
}

extern "C" void kernel_launch(void* const* d_in, const int* in_sizes, int n_in,
                              void* d_out, int out_size)
{
    const float* x_num  = (const float*)d_in[0];
    const float* cand   = (const float*)d_in[1];
    const float* cy     = (const float*)d_in[2];
    const float* lin_W  = (const float*)d_in[3];
    const float* lin_b  = (const float*)d_in[4];
    const float* e_W1   = (const float*)d_in[5];
    const float* e_b1   = (const float*)d_in[6];
    const float* e_W2   = (const float*)d_in[7];
    const float* e_b2   = (const float*)d_in[8];
    const float* mix_g  = (const float*)d_in[9];
    const float* mix_b  = (const float*)d_in[10];
    const float* K_W    = (const float*)d_in[11];
    const float* K_b    = (const float*)d_in[12];
    const float* lab_W  = (const float*)d_in[13];
    const float* lab_b  = (const float*)d_in[14];
    const float* T_W1   = (const float*)d_in[15];
    const float* T_b1   = (const float*)d_in[16];
    const float* T_W2   = (const float*)d_in[17];
    const float* p_ln_g = (const float*)d_in[18];
    const float* p_ln_b = (const float*)d_in[19];
    const float* p_W1   = (const float*)d_in[20];
    const float* p_b1   = (const float*)d_in[21];
    const float* p_W2   = (const float*)d_in[22];
    const float* p_b2   = (const float*)d_in[23];
    const float* h_ln_g = (const float*)d_in[24];
    const float* h_ln_b = (const float*)d_in[25];
    const float* h_W    = (const float*)d_in[26];
    const float* h_b    = (const float*)d_in[27];
    float* out = (float*)d_out;

    float* p_h     = devptr<float>(g_h);
    float* p_k     = devptr<float>(g_k);
    float* p_cproj = devptr<float>(g_cproj);
    float* p_cnorm = devptr<float>(g_cnorm);
    float* p_d2    = devptr<float>(g_d2);
    float* p_hx    = devptr<float>(g_hx);
    float* p_kx    = devptr<float>(g_kx);
    float* p_kproj = devptr<float>(g_kproj);
    float* p_kxn   = devptr<float>(g_kxn);
    int*   p_idx   = devptr<int>(g_idx);
    float* p_probs = devptr<float>(g_probs);
    float* p_ybar  = devptr<float>(g_ybar);
    float* p_x2    = devptr<float>(g_x2);
    float* p_x3    = devptr<float>(g_x3);

    bf16 *candh = devptr<bf16>(g_candh), *candl = devptr<bf16>(g_candl);
    bf16 *hh = devptr<bf16>(g_hh),   *hl = devptr<bf16>(g_hl);
    bf16 *th = devptr<bf16>(g_th),   *tl = devptr<bf16>(g_tl);
    bf16 *hnh = devptr<bf16>(g_hnh), *hnl = devptr<bf16>(g_hnl);
    bf16 *kh = devptr<bf16>(g_kh),   *kl = devptr<bf16>(g_kl);
    bf16 *xh = devptr<bf16>(g_xh),   *xl = devptr<bf16>(g_xl);
    bf16 *hxh = devptr<bf16>(g_hxh), *hxl = devptr<bf16>(g_hxl);
    bf16 *txh = devptr<bf16>(g_txh), *txl = devptr<bf16>(g_txl);
    bf16 *xnh = devptr<bf16>(g_xnh), *xnl = devptr<bf16>(g_xnl);
    bf16 *kxh = devptr<bf16>(g_kxh), *kxl = devptr<bf16>(g_kxl);
    bf16 *sh_ = devptr<bf16>(g_sh),  *sl_ = devptr<bf16>(g_sl);

    bf16 *wlinh = devptr<bf16>(g_wlinh), *wlinl = devptr<bf16>(g_wlinl);
    bf16 *we1h = devptr<bf16>(g_we1h),   *we1l = devptr<bf16>(g_we1l);
    bf16 *we2h = devptr<bf16>(g_we2h),   *we2l = devptr<bf16>(g_we2l);
    bf16 *wKh = devptr<bf16>(g_wKh),     *wKl = devptr<bf16>(g_wKl);
    bf16 *wT1h = devptr<bf16>(g_wT1h),   *wT1l = devptr<bf16>(g_wT1l);
    bf16 *wT2h = devptr<bf16>(g_wT2h),   *wT2l = devptr<bf16>(g_wT2l);
    bf16 *wp1h = devptr<bf16>(g_wp1h),   *wp1l = devptr<bf16>(g_wp1l);
    bf16 *wp2h = devptr<bf16>(g_wp2h),   *wp2l = devptr<bf16>(g_wp2l);

    // ---- one-time prep: split inputs + split/transpose weights --------------
    split4_k<<<(NC * FD / 4 + 255) / 256, 256>>>(cand, candh, candl, (long)NC * FD);
    split4_k<<<(BSZ * FD / 4 + 255) / 256, 256>>>(x_num, xh, xl, (long)BSZ * FD);
    {
        dim3 blk(32, 8);
        wsplitT_k<<<dim3(DD / 32, FD / 32), blk>>>(lin_W, FD, DD, wlinh, wlinl);
        wsplitT_k<<<dim3(DBD / 32, DD / 32), blk>>>(e_W1, DD, DBD, we1h, we1l);
        wsplitT_k<<<dim3(DD / 32, DBD / 32), blk>>>(e_W2, DBD, DD, we2h, we2l);
        wsplitT_k<<<dim3(DD / 32, DD / 32), blk>>>(K_W, DD, DD, wKh, wKl);
        wsplitT_k<<<dim3(DBD / 32, DD / 32), blk>>>(T_W1, DD, DBD, wT1h, wT1l);
        wsplitT_k<<<dim3(DD / 32, DBD / 32), blk>>>(T_W2, DBD, DD, wT2h, wT2l);
        wsplitT_k<<<dim3(DBD / 32, DD / 32), blk>>>(p_W1, DD, DBD, wp1h, wp1l);
        wsplitT_k<<<dim3(DD / 32, DBD / 32), blk>>>(p_W2, DBD, DD, wp2h, wp2l);
    }

    // ---- candidate encoder -----------------------------------------------
    launch_gemm<0, true, true>(NC, DD, FD, candh, candl, wlinh, wlinl,
                               lin_b, nullptr, nullptr, nullptr, p_h, hh, hl);
    launch_gemm<1, false, true>(NC, DBD, DD, hh, hl, we1h, we1l,
                                e_b1, nullptr, nullptr, nullptr, nullptr, th, tl);
    launch_gemm<2, true, false>(NC, DD, DBD, th, tl, we2h, we2l,
                                e_b2, p_h, nullptr, nullptr, p_h, nullptr, nullptr);
    ln512_split_k<<<NC, 256>>>(p_h, mix_g, mix_b, hnh, hnl);
    launch_gemm<0, true, true>(NC, DD, DD, hnh, hnl, wKh, wKl,
                               K_b, nullptr, nullptr, nullptr, p_k, kh, kl);
    launch_gemm<0, true, false>(NC, DBD, DD, kh, kl, wT1h, wT1l,
                                nullptr, nullptr, nullptr, nullptr, p_cproj, nullptr, nullptr);
    rownorm512_k<<<NC, 256>>>(p_k, p_cnorm);

    // ---- query encoder ----------------------------------------------------
    launch_gemm<0, true, true>(BSZ, DD, FD, xh, xl, wlinh, wlinl,
                               lin_b, nullptr, nullptr, nullptr, p_hx, hxh, hxl);
    launch_gemm<1, false, true>(BSZ, DBD, DD, hxh, hxl, we1h, we1l,
                                e_b1, nullptr, nullptr, nullptr, nullptr, txh, txl);
    launch_gemm<2, true, false>(BSZ, DD, DBD, txh, txl, we2h, we2l,
                                e_b2, p_hx, nullptr, nullptr, p_hx, nullptr, nullptr);
    ln512_split_k<<<BSZ, 256>>>(p_hx, mix_g, mix_b, xnh, xnl);
    launch_gemm<0, true, true>(BSZ, DD, DD, xnh, xnl, wKh, wKl,
                               K_b, nullptr, nullptr, nullptr, p_kx, kxh, kxl);
    launch_gemm<0, true, false>(BSZ, DBD, DD, kxh, kxl, wT1h, wT1l,
                                T_b1, nullptr, nullptr, nullptr, p_kproj, nullptr, nullptr);
    rownorm512_k<<<BSZ, 256>>>(p_kx, p_kxn);

    // ---- kNN scores + top-96 ----------------------------------------------
    launch_gemm<3, true, false>(BSZ, NC, DD, kxh, kxl, kh, kl,
                                nullptr, nullptr, p_kxn, p_cnorm, p_d2, nullptr, nullptr);
    topk96_k<<<BSZ, 256>>>(p_d2, p_idx);
    softmax96_k<<<BSZ, 128>>>(p_d2, p_idx, cy, p_probs, p_ybar);

    // ---- context aggregation ----------------------------------------------
    ctxsum_split_k<<<BSZ, 1024>>>(p_kproj, p_cproj, p_idx, p_probs, sh_, sl_);
    launch_gemm<4, true, false>(BSZ, DD, DBD, sh_, sl_, wT2h, wT2l,
                                lab_W, p_hx, p_ybar, lab_b, p_x2, nullptr, nullptr);

    // ---- predictor block + head -------------------------------------------
    ln512_split_k<<<BSZ, 256>>>(p_x2, p_ln_g, p_ln_b, xnh, xnl);
    launch_gemm<1, false, true>(BSZ, DBD, DD, xnh, xnl, wp1h, wp1l,
                                p_b1, nullptr, nullptr, nullptr, nullptr, txh, txl);
    launch_gemm<2, true, false>(BSZ, DD, DBD, txh, txl, wp2h, wp2l,
                                p_b2, p_x2, nullptr, nullptr, p_x3, nullptr, nullptr);
    head512_k<<<BSZ, 256>>>(p_x3, h_ln_g, h_ln_b, h_W, h_b, out);

    (void)in_sizes; (void)n_in; (void)out_size;
}

// round 8
// speedup vs baseline: 2.5528x; 1.0147x over previous
#include <cuda_runtime.h>
#include <cuda_bf16.h>
#include <cstdint>

// Problem constants (fixed by the dataset)
#define NC  65536   // candidates
#define BSZ 1024    // batch
#define FD  64      // input features
#define DD  512     // model dim
#define DBD 1024    // hidden dim
#define CC  96      // context size

typedef __nv_bfloat16 bf16;

// ---------------- device scratch (allocation-free rule: __device__ globals) ----
__device__ float g_h    [(long)NC*DD];
__device__ float g_k    [(long)NC*DD];
__device__ float g_cproj[(long)NC*DBD];
__device__ float g_cnorm[NC];
__device__ float g_d2   [(long)BSZ*NC];
__device__ float g_hx   [BSZ*DD];
__device__ float g_kx   [BSZ*DD];
__device__ float g_kproj[BSZ*DBD];
__device__ float g_kxn  [BSZ];
__device__ int   g_idx  [BSZ*CC];
__device__ float g_probs[BSZ*CC];
__device__ float g_ybar [BSZ];
__device__ float g_x2   [BSZ*DD];
__device__ float g_x3   [BSZ*DD];

// split bf16 activation buffers (hi/lo)
__device__ bf16 g_candh[(long)NC*FD],  g_candl[(long)NC*FD];
__device__ bf16 g_hh   [(long)NC*DD],  g_hl   [(long)NC*DD];
__device__ bf16 g_th   [(long)NC*DBD], g_tl   [(long)NC*DBD];
__device__ bf16 g_hnh  [(long)NC*DD],  g_hnl  [(long)NC*DD];
__device__ bf16 g_kh   [(long)NC*DD],  g_kl   [(long)NC*DD];
__device__ bf16 g_xh   [BSZ*FD],  g_xl   [BSZ*FD];
__device__ bf16 g_hxh  [BSZ*DD],  g_hxl  [BSZ*DD];
__device__ bf16 g_txh  [BSZ*DBD], g_txl  [BSZ*DBD];
__device__ bf16 g_xnh  [BSZ*DD],  g_xnl  [BSZ*DD];
__device__ bf16 g_kxh  [BSZ*DD],  g_kxl  [BSZ*DD];
__device__ bf16 g_sh   [BSZ*DBD], g_sl   [BSZ*DBD];

// split + transposed weights [N,K]
__device__ bf16 g_wlinh[DD*FD],   g_wlinl[DD*FD];
__device__ bf16 g_we1h [DBD*DD],  g_we1l [DBD*DD];
__device__ bf16 g_we2h [DD*DBD],  g_we2l [DD*DBD];
__device__ bf16 g_wKh  [DD*DD],   g_wKl  [DD*DD];
__device__ bf16 g_wT1h [DBD*DD],  g_wT1l [DBD*DD];
__device__ bf16 g_wT2h [DD*DBD],  g_wT2l [DD*DBD];
__device__ bf16 g_wp1h [DBD*DD],  g_wp1l [DBD*DD];
__device__ bf16 g_wp2h [DD*DBD],  g_wp2l [DD*DBD];

// ---------------- helpers -------------------------------------------------------
__device__ __forceinline__ void split1(float x, bf16 &h, bf16 &l) {
    h = __float2bfloat16_rn(x);
    l = __float2bfloat16_rn(x - __bfloat162float(h));
}

__device__ __forceinline__ void mma_bf16(float c[4], const unsigned a[4], const unsigned b[2]) {
    asm volatile(
        "mma.sync.aligned.m16n8k16.row.col.f32.bf16.bf16.f32 "
        "{%0,%1,%2,%3}, {%4,%5,%6,%7}, {%8,%9}, {%0,%1,%2,%3};"
        : "+f"(c[0]), "+f"(c[1]), "+f"(c[2]), "+f"(c[3])
        : "r"(a[0]), "r"(a[1]), "r"(a[2]), "r"(a[3]), "r"(b[0]), "r"(b[1]));
}

__device__ __forceinline__ void cp16s(unsigned saddr, const void* gsrc) {
    asm volatile("cp.async.cg.shared.global [%0], [%1], 16;\n" :: "r"(saddr), "l"(gsrc));
}

__device__ __forceinline__ void ldsm4(unsigned &r0, unsigned &r1, unsigned &r2,
                                      unsigned &r3, unsigned addr) {
    asm volatile("ldmatrix.sync.aligned.m8n8.x4.shared.b16 {%0,%1,%2,%3}, [%4];"
                 : "=r"(r0), "=r"(r1), "=r"(r2), "=r"(r3) : "r"(addr));
}

__device__ __forceinline__ float blockSum(float v, float* sh) {
    __syncthreads();
    int lane = threadIdx.x & 31, w = threadIdx.x >> 5;
#pragma unroll
    for (int o = 16; o; o >>= 1) v += __shfl_xor_sync(0xffffffffu, v, o);
    if (lane == 0) sh[w] = v;
    __syncthreads();
    if (threadIdx.x == 0) {
        float s = 0.f; int nw = blockDim.x >> 5;
        for (int i = 0; i < nw; i++) s += sh[i];
        sh[32] = s;
    }
    __syncthreads();
    return sh[32];
}

__device__ __forceinline__ float blockMax(float v, float* sh) {
    __syncthreads();
    int lane = threadIdx.x & 31, w = threadIdx.x >> 5;
#pragma unroll
    for (int o = 16; o; o >>= 1) v = fmaxf(v, __shfl_xor_sync(0xffffffffu, v, o));
    if (lane == 0) sh[w] = v;
    __syncthreads();
    if (threadIdx.x == 0) {
        float s = -3.4e38f; int nw = blockDim.x >> 5;
        for (int i = 0; i < nw; i++) s = fmaxf(s, sh[i]);
        sh[32] = s;
    }
    __syncthreads();
    return sh[32];
}

// ---------------- split-bf16 tensor-core GEMM (ldmatrix + 3-stage cp.async) ----
// A: [M,K] hi/lo bf16 k-contiguous; B: [N,K] hi/lo bf16. C = A·B^T, 3-term
// compensated (hh + hl + lh), fp32 accumulation.
// Block 128x128, K-chunk 32, 3 stages, ONE barrier per chunk, 8 warps 2(M)x4(N).
// SMEM: 64B rows, SW64 swizzle -> conflict-free ldmatrix.
// MODE 0: +bias   MODE 1: relu(+bias)   MODE 2: +bias+res
// MODE 3: rowv[m]+colv[n]-2*AB          MODE 4: AB+res+rowv[m]*bias[n]+colv[n]
#define GS_STAGE 32768                   // 4 buffers x 8KB
#define GS_SMEM  (3 * GS_STAGE)

template<int MODE, bool WF32, bool WSPLIT>
__global__ void __launch_bounds__(256, 2) gemm_bf16s_k(
    int M, int N, int K,
    const bf16* __restrict__ Ahg, const bf16* __restrict__ Alg,
    const bf16* __restrict__ Bhg, const bf16* __restrict__ Blg,
    const float* __restrict__ bias, const float* __restrict__ res,
    const float* __restrict__ rowv, const float* __restrict__ colv,
    float* __restrict__ C, bf16* __restrict__ Chi, bf16* __restrict__ Clo)
{
    extern __shared__ __align__(1024) char smem[];
    const unsigned sbase = (unsigned)__cvta_generic_to_shared(smem);

    const int tid  = threadIdx.x;
    const int lane = tid & 31;
    const int wid  = tid >> 5;
    const int wm   = (wid & 1) * 64;
    const int wn   = (wid >> 1) * 32;
    const int grp  = lane >> 2;
    const int thr  = lane & 3;

    const long rowBase = (long)blockIdx.y * 128;
    const long colBase = (long)blockIdx.x * 128;

    float acc[4][4][4];
#pragma unroll
    for (int mi = 0; mi < 4; mi++)
#pragma unroll
        for (int ni = 0; ni < 4; ni++)
#pragma unroll
            for (int j = 0; j < 4; j++) acc[mi][ni][j] = 0.f;

    const int T = K >> 5;    // 32-elem chunks

    // ---- stage fill: chunk t into stage s ---------------------------------
    auto fill = [&](int s, int t) {
        const int k0 = t << 5;
        const unsigned sb = sbase + (unsigned)s * GS_STAGE;
#pragma unroll
        for (int i = 0; i < 2; i++) {
            int q = tid + i * 256;
            int r = q >> 2, c = q & 3;
            int off = r * 64 + c * 16;
            int sw  = off ^ ((off >> 3) & 0x30);
            const long ao = (rowBase + r) * (long)K + k0 + c * 8;
            const long bo = (colBase + r) * (long)K + k0 + c * 8;
            cp16s(sb + sw,          Ahg + ao);
            cp16s(sb + 8192 + sw,   Alg + ao);
            cp16s(sb + 16384 + sw,  Bhg + bo);
            cp16s(sb + 24576 + sw,  Blg + bo);
        }
        asm volatile("cp.async.commit_group;" ::: "memory");
    };

    // lane-derived ldmatrix address components
    const int aRow16 = lane & 15;                   // m offset within 16
    const int aKx    = (lane & 16) ? 16 : 0;        // byte offset (k +8 elems)
    const int bRowO  = (lane & 7) + ((lane & 16) ? 8 : 0);
    const int bKx    = (lane & 8) ? 16 : 0;

    fill(0, 0);
    if (T > 1) fill(1, 1);

    for (int t = 0; t < T; t++) {
        if (t < T - 1) asm volatile("cp.async.wait_group 1;" ::: "memory");
        else           asm volatile("cp.async.wait_group 0;" ::: "memory");
        // Single barrier per chunk. After it: (a) chunk t's data is visible to
        // all warps; (b) every warp finished computing chunk t-1, so buffer
        // (t+2)%3 == (t-1)%3 is safe to overwrite.
        __syncthreads();
        if (t + 2 < T) fill((t + 2) % 3, t + 2);

        const unsigned ab  = sbase + (unsigned)(t % 3) * GS_STAGE;
        const unsigned alb = ab + 8192, bb = ab + 16384, blb = ab + 24576;

#pragma unroll
        for (int s16 = 0; s16 < 64; s16 += 32) {      // two k16 sub-steps (bytes)
            unsigned ah[4][4], al[4][4];
#pragma unroll
            for (int mi = 0; mi < 4; mi++) {
                int rowb = (wm + mi * 16 + aRow16) * 64;
                unsigned msk = (unsigned)((rowb >> 3) & 0x30);
                ldsm4(ah[mi][0], ah[mi][1], ah[mi][2], ah[mi][3],
                      (ab + rowb + s16 + aKx) ^ msk);
                ldsm4(al[mi][0], al[mi][1], al[mi][2], al[mi][3],
                      (alb + rowb + s16 + aKx) ^ msk);
            }
#pragma unroll
            for (int p = 0; p < 2; p++) {
                int rowb = (wn + p * 16 + bRowO) * 64;
                unsigned msk = (unsigned)((rowb >> 3) & 0x30);
                unsigned bh[4], bl[4];
                ldsm4(bh[0], bh[1], bh[2], bh[3], (bb + rowb + s16 + bKx) ^ msk);
                ldsm4(bl[0], bl[1], bl[2], bl[3], (blb + rowb + s16 + bKx) ^ msk);
#pragma unroll
                for (int mi = 0; mi < 4; mi++) {
                    mma_bf16(acc[mi][2 * p],     ah[mi], &bh[0]);
                    mma_bf16(acc[mi][2 * p],     ah[mi], &bl[0]);
                    mma_bf16(acc[mi][2 * p],     al[mi], &bh[0]);
                    mma_bf16(acc[mi][2 * p + 1], ah[mi], &bh[2]);
                    mma_bf16(acc[mi][2 * p + 1], ah[mi], &bl[2]);
                    mma_bf16(acc[mi][2 * p + 1], al[mi], &bh[2]);
                }
            }
        }
    }

    // ---- epilogue ----------------------------------------------------------
#pragma unroll
    for (int mi = 0; mi < 4; mi++) {
#pragma unroll
        for (int half = 0; half < 2; half++) {
            const long rr = rowBase + wm + mi * 16 + grp + half * 8;
            const float rv = (MODE == 3 || MODE == 4) ? rowv[rr] : 0.f;
#pragma unroll
            for (int ni = 0; ni < 4; ni++) {
                const long c = colBase + wn + ni * 8 + thr * 2;
                float o0 = acc[mi][ni][half * 2 + 0];
                float o1 = acc[mi][ni][half * 2 + 1];
                if (MODE == 0 || MODE == 1 || MODE == 2) {
                    if (bias) { o0 += bias[c]; o1 += bias[c + 1]; }
                }
                if (MODE == 2) {
                    o0 += res[rr * N + c]; o1 += res[rr * N + c + 1];
                }
                if (MODE == 1) { o0 = fmaxf(o0, 0.f); o1 = fmaxf(o1, 0.f); }
                if (MODE == 3) {
                    o0 = rv + colv[c]     - 2.f * o0;
                    o1 = rv + colv[c + 1] - 2.f * o1;
                }
                if (MODE == 4) {
                    o0 = o0 + res[rr * N + c]     + rv * bias[c]     + colv[c];
                    o1 = o1 + res[rr * N + c + 1] + rv * bias[c + 1] + colv[c + 1];
                }
                if (WF32)
                    *(float2*)(C + rr * N + c) = make_float2(o0, o1);
                if (WSPLIT) {
                    bf16 h0, l0, h1, l1;
                    split1(o0, h0, l0);
                    split1(o1, h1, l1);
                    ushort2 hp, lp;
                    hp.x = __bfloat16_as_ushort(h0); hp.y = __bfloat16_as_ushort(h1);
                    lp.x = __bfloat16_as_ushort(l0); lp.y = __bfloat16_as_ushort(l1);
                    *(ushort2*)&Chi[rr * N + c] = hp;
                    *(ushort2*)&Clo[rr * N + c] = lp;
                }
            }
        }
    }
}

// ---------------- split fp32 -> bf16 hi/lo (same layout) -----------------------
__global__ void split4_k(const float* __restrict__ in, bf16* __restrict__ oh,
                         bf16* __restrict__ ol, long n)
{
    long i = ((long)blockIdx.x * blockDim.x + threadIdx.x) * 4;
    if (i >= n) return;
    float4 v = *(const float4*)(in + i);
    bf16 h0,l0,h1,l1,h2,l2,h3,l3;
    split1(v.x,h0,l0); split1(v.y,h1,l1); split1(v.z,h2,l2); split1(v.w,h3,l3);
    ushort4 hp, lp;
    hp.x=__bfloat16_as_ushort(h0); hp.y=__bfloat16_as_ushort(h1);
    hp.z=__bfloat16_as_ushort(h2); hp.w=__bfloat16_as_ushort(h3);
    lp.x=__bfloat16_as_ushort(l0); lp.y=__bfloat16_as_ushort(l1);
    lp.z=__bfloat16_as_ushort(l2); lp.w=__bfloat16_as_ushort(l3);
    *(ushort4*)&oh[i] = hp;
    *(ushort4*)&ol[i] = lp;
}

// ---------------- weight split + transpose: [K,N] fp32 -> [N,K] bf16 hi/lo -----
__global__ void wsplitT_k(const float* __restrict__ in, int K, int N,
                          bf16* __restrict__ oh, bf16* __restrict__ ol)
{
    __shared__ float tile[32][33];
    int n0 = blockIdx.x * 32, k0 = blockIdx.y * 32;
    int tx = threadIdx.x, ty = threadIdx.y;   // 32 x 8
#pragma unroll
    for (int j = 0; j < 4; j++)
        tile[ty + j * 8][tx] = in[(long)(k0 + ty + j * 8) * N + n0 + tx];
    __syncthreads();
#pragma unroll
    for (int j = 0; j < 4; j++) {
        float v = tile[tx][ty + j * 8];
        bf16 h, l; split1(v, h, l);
        long o = (long)(n0 + ty + j * 8) * K + k0 + tx;
        oh[o] = h; ol[o] = l;
    }
}

// ---------------- layernorm (width 512) -> split bf16 --------------------------
__global__ void ln512_split_k(const float* __restrict__ in, const float* __restrict__ g,
                              const float* __restrict__ b,
                              bf16* __restrict__ oh, bf16* __restrict__ ol)
{
    __shared__ float sh[33];
    const long row = blockIdx.x;
    const float* x = in + row * DD;
    int t = threadIdx.x;
    float a = x[t], c = x[t + 256];
    float m = blockSum(a + c, sh) * (1.f / DD);
    float d0 = a - m, d1 = c - m;
    float var = blockSum(d0 * d0 + d1 * d1, sh) * (1.f / DD);
    float inv = rsqrtf(var + 1e-5f);
    float o0 = d0 * inv * g[t]       + b[t];
    float o1 = d1 * inv * g[t + 256] + b[t + 256];
    bf16 h, l;
    split1(o0, h, l); oh[row * DD + t] = h;       ol[row * DD + t] = l;
    split1(o1, h, l); oh[row * DD + t + 256] = h; ol[row * DD + t + 256] = l;
}

// ---------------- row squared-norms (width 512) --------------------------------
__global__ void rownorm512_k(const float* __restrict__ in, float* __restrict__ out)
{
    __shared__ float sh[33];
    const long row = blockIdx.x;
    const float* x = in + row * DD;
    int t = threadIdx.x;
    float a = x[t], c = x[t + 256];
    float s = blockSum(a * a + c * c, sh);
    if (t == 0) out[row] = s;
}

// ---------------- top-96 via 8-bit radix select on monotone float keys --------
__device__ __forceinline__ unsigned fkey(float f) {
    unsigned u = __float_as_uint(f);
    return (u & 0x80000000u) ? ~u : (u | 0x80000000u);
}

__global__ void topk96_k(const float* __restrict__ d2, int* __restrict__ idxo)
{
    const int b = blockIdx.x;
    const float* row = d2 + (long)b * NC;
    __shared__ int hist[256];
    __shared__ unsigned s_prefix;
    __shared__ int s_k, s_below;
    const int tid = threadIdx.x;
    if (tid == 0) { s_prefix = 0u; s_k = CC; s_below = 0; }
    __syncthreads();

#pragma unroll
    for (int p = 0; p < 4; p++) {
        const int shift = 24 - p * 8;
        const unsigned pmask = (p == 0) ? 0u : (0xFFFFFFFFu << (shift + 8));
        hist[tid] = 0;
        __syncthreads();
        const unsigned pref = s_prefix;
        for (int i = tid; i < NC; i += 256) {
            unsigned u = fkey(row[i]);
            if ((u & pmask) == pref) atomicAdd(&hist[(u >> shift) & 255], 1);
        }
        __syncthreads();
        if (tid == 0) {
            int cum = 0, kk = s_k;
            for (int bin = 0; bin < 256; bin++) {
                int h = hist[bin];
                if (cum + h >= kk) {
                    s_prefix = pref | ((unsigned)bin << shift);
                    s_k = kk - cum;
                    s_below += cum;
                    break;
                }
                cum += h;
            }
        }
        __syncthreads();
    }
    const unsigned T = s_prefix;
    const int below = s_below;
    __shared__ int cl, ce;
    if (tid == 0) { cl = 0; ce = 0; }
    __syncthreads();
    for (int i = tid; i < NC; i += 256) {
        unsigned u = fkey(row[i]);
        if (u < T) {
            int pos = atomicAdd(&cl, 1);
            idxo[b * CC + pos] = i;
        } else if (u == T) {
            int pos = atomicAdd(&ce, 1);
            if (below + pos < CC) idxo[b * CC + below + pos] = i;
        }
    }
}

// ---------------- softmax over gathered sims + ybar -----------------------------
__global__ void softmax96_k(const float* __restrict__ d2, const int* __restrict__ idx,
                            const float* __restrict__ cy, float* __restrict__ probs,
                            float* __restrict__ ybar)
{
    __shared__ float sh[33];
    const int b = blockIdx.x, t = threadIdx.x;   // 128 threads
    int id = (t < CC) ? idx[b * CC + t] : 0;
    float sim = (t < CC) ? -d2[(long)b * NC + id] : -3.4e38f;
    float mx = blockMax(sim, sh);
    float e = (t < CC) ? expf(sim - mx) : 0.f;
    float s = blockSum(e, sh);
    float p = e / s;
    if (t < CC) probs[b * CC + t] = p;
    float yv = (t < CC) ? p * cy[id] : 0.f;
    float yb = blockSum(yv, sh);
    if (t == 0) ybar[b] = yb;
}

// ---------- s[b,:] = sum_c probs * relu(kproj - cproj[idx]), split output -------
__global__ void ctxsum_split_k(const float* __restrict__ kproj, const float* __restrict__ cproj,
                               const int* __restrict__ idx, const float* __restrict__ probs,
                               bf16* __restrict__ oh, bf16* __restrict__ ol)
{
    const int b = blockIdx.x, j = threadIdx.x;   // 1024 threads
    __shared__ int   si[CC];
    __shared__ float sp[CC];
    if (j < CC) { si[j] = idx[b * CC + j]; sp[j] = probs[b * CC + j]; }
    __syncthreads();
    float kp = kproj[(long)b * DBD + j];
    float acc = 0.f;
#pragma unroll 4
    for (int c = 0; c < CC; c++) {
        float v = kp - cproj[(long)si[c] * DBD + j];
        acc += sp[c] * fmaxf(v, 0.f);
    }
    bf16 h, l; split1(acc, h, l);
    oh[(long)b * DBD + j] = h;
    ol[(long)b * DBD + j] = l;
}

// ---------------- head: relu(ln(x)) @ h_W + h_b ---------------------------------
__global__ void head512_k(const float* __restrict__ in, const float* __restrict__ g,
                          const float* __restrict__ bb, const float* __restrict__ hW,
                          const float* __restrict__ hb, float* __restrict__ out)
{
    __shared__ float sh[33];
    const long row = blockIdx.x;
    const float* x = in + row * DD;
    int t = threadIdx.x;
    float a = x[t], c = x[t + 256];
    float m = blockSum(a + c, sh) * (1.f / DD);
    float d0 = a - m, d1 = c - m;
    float v = blockSum(d0 * d0 + d1 * d1, sh) * (1.f / DD);
    float inv = rsqrtf(v + 1e-5f);
    float s0 = fmaxf(d0 * inv * g[t] + bb[t], 0.f) * hW[t];
    float s1 = fmaxf(d1 * inv * g[t + 256] + bb[t + 256], 0.f) * hW[t + 256];
    float tot = blockSum(s0 + s1, sh);
    if (t == 0) out[row] = tot + hb[0];
}

// ---------------- host side -----------------------------------------------------
template<typename T>
static T* devptr(const void* sym) {
    void* p = nullptr;
    cudaGetSymbolAddress(&p, sym);
    return (T*)p;
}

template<int MODE, bool WF32, bool WSPLIT>
static void launch_gemm(int M, int N, int K,
                        const bf16* Ah, const bf16* Al, const bf16* Bh, const bf16* Bl,
                        const float* bias, const float* res,
                        const float* rowv, const float* colv,
                        float* C, bf16* Chi, bf16* Clo) {
    cudaFuncSetAttribute(gemm_bf16s_k<MODE, WF32, WSPLIT>,
                         cudaFuncAttributeMaxDynamicSharedMemorySize, GS_SMEM);
    dim3 grid(N / 128, M / 128);
    gemm_bf16s_k<MODE, WF32, WSPLIT><<<grid, 256, GS_SMEM>>>(
        M, N, K, Ah, Al, Bh, Bl, bias, res, rowv, colv, C, Chi, Clo);
}

extern "C" void kernel_launch(void* const* d_in, const int* in_sizes, int n_in,
                              void* d_out, int out_size)
{
    const float* x_num  = (const float*)d_in[0];
    const float* cand   = (const float*)d_in[1];
    const float* cy     = (const float*)d_in[2];
    const float* lin_W  = (const float*)d_in[3];
    const float* lin_b  = (const float*)d_in[4];
    const float* e_W1   = (const float*)d_in[5];
    const float* e_b1   = (const float*)d_in[6];
    const float* e_W2   = (const float*)d_in[7];
    const float* e_b2   = (const float*)d_in[8];
    const float* mix_g  = (const float*)d_in[9];
    const float* mix_b  = (const float*)d_in[10];
    const float* K_W    = (const float*)d_in[11];
    const float* K_b    = (const float*)d_in[12];
    const float* lab_W  = (const float*)d_in[13];
    const float* lab_b  = (const float*)d_in[14];
    const float* T_W1   = (const float*)d_in[15];
    const float* T_b1   = (const float*)d_in[16];
    const float* T_W2   = (const float*)d_in[17];
    const float* p_ln_g = (const float*)d_in[18];
    const float* p_ln_b = (const float*)d_in[19];
    const float* p_W1   = (const float*)d_in[20];
    const float* p_b1   = (const float*)d_in[21];
    const float* p_W2   = (const float*)d_in[22];
    const float* p_b2   = (const float*)d_in[23];
    const float* h_ln_g = (const float*)d_in[24];
    const float* h_ln_b = (const float*)d_in[25];
    const float* h_W    = (const float*)d_in[26];
    const float* h_b    = (const float*)d_in[27];
    float* out = (float*)d_out;

    float* p_h     = devptr<float>(g_h);
    float* p_k     = devptr<float>(g_k);
    float* p_cproj = devptr<float>(g_cproj);
    float* p_cnorm = devptr<float>(g_cnorm);
    float* p_d2    = devptr<float>(g_d2);
    float* p_hx    = devptr<float>(g_hx);
    float* p_kx    = devptr<float>(g_kx);
    float* p_kproj = devptr<float>(g_kproj);
    float* p_kxn   = devptr<float>(g_kxn);
    int*   p_idx   = devptr<int>(g_idx);
    float* p_probs = devptr<float>(g_probs);
    float* p_ybar  = devptr<float>(g_ybar);
    float* p_x2    = devptr<float>(g_x2);
    float* p_x3    = devptr<float>(g_x3);

    bf16 *candh = devptr<bf16>(g_candh), *candl = devptr<bf16>(g_candl);
    bf16 *hh = devptr<bf16>(g_hh),   *hl = devptr<bf16>(g_hl);
    bf16 *th = devptr<bf16>(g_th),   *tl = devptr<bf16>(g_tl);
    bf16 *hnh = devptr<bf16>(g_hnh), *hnl = devptr<bf16>(g_hnl);
    bf16 *kh = devptr<bf16>(g_kh),   *kl = devptr<bf16>(g_kl);
    bf16 *xh = devptr<bf16>(g_xh),   *xl = devptr<bf16>(g_xl);
    bf16 *hxh = devptr<bf16>(g_hxh), *hxl = devptr<bf16>(g_hxl);
    bf16 *txh = devptr<bf16>(g_txh), *txl = devptr<bf16>(g_txl);
    bf16 *xnh = devptr<bf16>(g_xnh), *xnl = devptr<bf16>(g_xnl);
    bf16 *kxh = devptr<bf16>(g_kxh), *kxl = devptr<bf16>(g_kxl);
    bf16 *sh_ = devptr<bf16>(g_sh),  *sl_ = devptr<bf16>(g_sl);

    bf16 *wlinh = devptr<bf16>(g_wlinh), *wlinl = devptr<bf16>(g_wlinl);
    bf16 *we1h = devptr<bf16>(g_we1h),   *we1l = devptr<bf16>(g_we1l);
    bf16 *we2h = devptr<bf16>(g_we2h),   *we2l = devptr<bf16>(g_we2l);
    bf16 *wKh = devptr<bf16>(g_wKh),     *wKl = devptr<bf16>(g_wKl);
    bf16 *wT1h = devptr<bf16>(g_wT1h),   *wT1l = devptr<bf16>(g_wT1l);
    bf16 *wT2h = devptr<bf16>(g_wT2h),   *wT2l = devptr<bf16>(g_wT2l);
    bf16 *wp1h = devptr<bf16>(g_wp1h),   *wp1l = devptr<bf16>(g_wp1l);
    bf16 *wp2h = devptr<bf16>(g_wp2h),   *wp2l = devptr<bf16>(g_wp2l);

    // ---- one-time prep: split inputs + split/transpose weights --------------
    split4_k<<<(NC * FD / 4 + 255) / 256, 256>>>(cand, candh, candl, (long)NC * FD);
    split4_k<<<(BSZ * FD / 4 + 255) / 256, 256>>>(x_num, xh, xl, (long)BSZ * FD);
    {
        dim3 blk(32, 8);
        wsplitT_k<<<dim3(DD / 32, FD / 32), blk>>>(lin_W, FD, DD, wlinh, wlinl);
        wsplitT_k<<<dim3(DBD / 32, DD / 32), blk>>>(e_W1, DD, DBD, we1h, we1l);
        wsplitT_k<<<dim3(DD / 32, DBD / 32), blk>>>(e_W2, DBD, DD, we2h, we2l);
        wsplitT_k<<<dim3(DD / 32, DD / 32), blk>>>(K_W, DD, DD, wKh, wKl);
        wsplitT_k<<<dim3(DBD / 32, DD / 32), blk>>>(T_W1, DD, DBD, wT1h, wT1l);
        wsplitT_k<<<dim3(DD / 32, DBD / 32), blk>>>(T_W2, DBD, DD, wT2h, wT2l);
        wsplitT_k<<<dim3(DBD / 32, DD / 32), blk>>>(p_W1, DD, DBD, wp1h, wp1l);
        wsplitT_k<<<dim3(DD / 32, DBD / 32), blk>>>(p_W2, DBD, DD, wp2h, wp2l);
    }

    // ---- candidate encoder -----------------------------------------------
    launch_gemm<0, true, true>(NC, DD, FD, candh, candl, wlinh, wlinl,
                               lin_b, nullptr, nullptr, nullptr, p_h, hh, hl);
    launch_gemm<1, false, true>(NC, DBD, DD, hh, hl, we1h, we1l,
                                e_b1, nullptr, nullptr, nullptr, nullptr, th, tl);
    launch_gemm<2, true, false>(NC, DD, DBD, th, tl, we2h, we2l,
                                e_b2, p_h, nullptr, nullptr, p_h, nullptr, nullptr);
    ln512_split_k<<<NC, 256>>>(p_h, mix_g, mix_b, hnh, hnl);
    launch_gemm<0, true, true>(NC, DD, DD, hnh, hnl, wKh, wKl,
                               K_b, nullptr, nullptr, nullptr, p_k, kh, kl);
    launch_gemm<0, true, false>(NC, DBD, DD, kh, kl, wT1h, wT1l,
                                nullptr, nullptr, nullptr, nullptr, p_cproj, nullptr, nullptr);
    rownorm512_k<<<NC, 256>>>(p_k, p_cnorm);

    // ---- query encoder ----------------------------------------------------
    launch_gemm<0, true, true>(BSZ, DD, FD, xh, xl, wlinh, wlinl,
                               lin_b, nullptr, nullptr, nullptr, p_hx, hxh, hxl);
    launch_gemm<1, false, true>(BSZ, DBD, DD, hxh, hxl, we1h, we1l,
                                e_b1, nullptr, nullptr, nullptr, nullptr, txh, txl);
    launch_gemm<2, true, false>(BSZ, DD, DBD, txh, txl, we2h, we2l,
                                e_b2, p_hx, nullptr, nullptr, p_hx, nullptr, nullptr);
    ln512_split_k<<<BSZ, 256>>>(p_hx, mix_g, mix_b, xnh, xnl);
    launch_gemm<0, true, true>(BSZ, DD, DD, xnh, xnl, wKh, wKl,
                               K_b, nullptr, nullptr, nullptr, p_kx, kxh, kxl);
    launch_gemm<0, true, false>(BSZ, DBD, DD, kxh, kxl, wT1h, wT1l,
                                T_b1, nullptr, nullptr, nullptr, p_kproj, nullptr, nullptr);
    rownorm512_k<<<BSZ, 256>>>(p_kx, p_kxn);

    // ---- kNN scores + top-96 ----------------------------------------------
    launch_gemm<3, true, false>(BSZ, NC, DD, kxh, kxl, kh, kl,
                                nullptr, nullptr, p_kxn, p_cnorm, p_d2, nullptr, nullptr);
    topk96_k<<<BSZ, 256>>>(p_d2, p_idx);
    softmax96_k<<<BSZ, 128>>>(p_d2, p_idx, cy, p_probs, p_ybar);

    // ---- context aggregation ----------------------------------------------
    ctxsum_split_k<<<BSZ, 1024>>>(p_kproj, p_cproj, p_idx, p_probs, sh_, sl_);
    launch_gemm<4, true, false>(BSZ, DD, DBD, sh_, sl_, wT2h, wT2l,
                                lab_W, p_hx, p_ybar, lab_b, p_x2, nullptr, nullptr);

    // ---- predictor block + head -------------------------------------------
    ln512_split_k<<<BSZ, 256>>>(p_x2, p_ln_g, p_ln_b, xnh, xnl);
    launch_gemm<1, false, true>(BSZ, DBD, DD, xnh, xnl, wp1h, wp1l,
                                p_b1, nullptr, nullptr, nullptr, nullptr, txh, txl);
    launch_gemm<2, true, false>(BSZ, DD, DBD, txh, txl, wp2h, wp2l,
                                p_b2, p_x2, nullptr, nullptr, p_x3, nullptr, nullptr);
    head512_k<<<BSZ, 256>>>(p_x3, h_ln_g, h_ln_b, h_W, h_b, out);

    (void)in_sizes; (void)n_in; (void)out_size;
}